// round 1
// baseline (speedup 1.0000x reference)
#include <cuda_runtime.h>
#include <math.h>

// ============================================================================
// Problem constants: B=2, S=2048, E=1024, H=16, D=64. M = B*S = 4096.
// Inputs (metadata order): x, Wq, bq, Wk, bk, Wv, bv, Wo, bo   (all fp32)
// Output: [B, S, E] fp32
// ============================================================================

#define E_DIM 1024
#define NH    16
#define HD    64
#define S_LEN 2048
#define MAX_M 4096

// Scratch (allocation rules forbid cudaMalloc; use device globals)
__device__ float g_q[MAX_M * E_DIM];
__device__ float g_k[MAX_M * E_DIM];
__device__ float g_v[MAX_M * E_DIM];
__device__ float g_attn[MAX_M * E_DIM];

// ============================================================================
// SGEMM:  C[m,n] = sum_k A[m,k] * W[n,k] + bias[n]
// A: [M,K] row-major, W: [N,K] row-major (torch Linear weight) -> TN gemm,
// both operands K-contiguous => coalesced loads.
// Tile: BM=128, BN=128, BK=16; 256 threads; 8x8 register tile per thread.
// ============================================================================

#define GBM 128
#define GBN 128
#define GBK 16
#define GTM 8
#define GTN 8

__device__ __forceinline__ void gemm_body(
    const float* __restrict__ A, const float* __restrict__ W,
    const float* __restrict__ bias, float* __restrict__ C,
    int M, int N, int K)
{
    __shared__ float As[GBK][GBM];
    __shared__ float Ws[GBK][GBN];

    const int tid  = threadIdx.x;
    const int bm   = blockIdx.y * GBM;
    const int bn   = blockIdx.x * GBN;
    const int tx   = tid & 15;   // n-direction (0..15)
    const int ty   = tid >> 4;   // m-direction (0..15)
    const int lrow = tid >> 2;        // 0..63
    const int lcol = (tid & 3) << 2;  // 0,4,8,12

    float acc[GTM][GTN];
#pragma unroll
    for (int i = 0; i < GTM; ++i)
#pragma unroll
        for (int j = 0; j < GTN; ++j) acc[i][j] = 0.0f;

    for (int kt = 0; kt < K; kt += GBK) {
        // Load A tile [BM x BK] and W tile [BN x BK], store k-major in smem
#pragma unroll
        for (int r = 0; r < 2; ++r) {
            const int row = lrow + r * 64;
            float4 av = *reinterpret_cast<const float4*>(
                &A[(size_t)(bm + row) * K + kt + lcol]);
            As[lcol + 0][row] = av.x;
            As[lcol + 1][row] = av.y;
            As[lcol + 2][row] = av.z;
            As[lcol + 3][row] = av.w;
            float4 wv = *reinterpret_cast<const float4*>(
                &W[(size_t)(bn + row) * K + kt + lcol]);
            Ws[lcol + 0][row] = wv.x;
            Ws[lcol + 1][row] = wv.y;
            Ws[lcol + 2][row] = wv.z;
            Ws[lcol + 3][row] = wv.w;
        }
        __syncthreads();

#pragma unroll
        for (int k = 0; k < GBK; ++k) {
            float rm[GTM], rn[GTN];
#pragma unroll
            for (int i = 0; i < GTM; ++i) rm[i] = As[k][ty * GTM + i];
#pragma unroll
            for (int j = 0; j < GTN; ++j) rn[j] = Ws[k][tx * GTN + j];
#pragma unroll
            for (int i = 0; i < GTM; ++i)
#pragma unroll
                for (int j = 0; j < GTN; ++j)
                    acc[i][j] = fmaf(rm[i], rn[j], acc[i][j]);
        }
        __syncthreads();
    }

    // Epilogue: add bias, vectorized store
    float bv[GTN];
#pragma unroll
    for (int j = 0; j < GTN; ++j) bv[j] = bias[bn + tx * GTN + j];

#pragma unroll
    for (int i = 0; i < GTM; ++i) {
        const int row = bm + ty * GTM + i;
#pragma unroll
        for (int j = 0; j < GTN; j += 4) {
            float4 v;
            v.x = acc[i][j + 0] + bv[j + 0];
            v.y = acc[i][j + 1] + bv[j + 1];
            v.z = acc[i][j + 2] + bv[j + 2];
            v.w = acc[i][j + 3] + bv[j + 3];
            *reinterpret_cast<float4*>(
                &C[(size_t)row * N + bn + tx * GTN + j]) = v;
        }
    }
}

// Fused QKV projection: blockIdx.z selects which of the 3 GEMMs.
// One launch = 3*256 = 768 blocks -> fills the chip instead of 3 tail-heavy launches.
__global__ __launch_bounds__(256) void gemm_qkv_kernel(
    const float* __restrict__ x,
    const float* __restrict__ Wq, const float* __restrict__ bq,
    const float* __restrict__ Wk, const float* __restrict__ bk,
    const float* __restrict__ Wv, const float* __restrict__ bv,
    int M)
{
    const float* W; const float* b; float* C;
    if (blockIdx.z == 0)      { W = Wq; b = bq; C = g_q; }
    else if (blockIdx.z == 1) { W = Wk; b = bk; C = g_k; }
    else                      { W = Wv; b = bv; C = g_v; }
    gemm_body(x, W, b, C, M, E_DIM, E_DIM);
}

// Output projection: attn @ Wo^T + bo
__global__ __launch_bounds__(256) void gemm_out_kernel(
    const float* __restrict__ Wo, const float* __restrict__ bo,
    float* __restrict__ out, int M)
{
    gemm_body(g_attn, Wo, bo, out, M, E_DIM, E_DIM);
}

// ============================================================================
// Flash-style attention, fp32.
// Grid: (S/128, B*H). Block: 128 threads, one query per thread.
// Per thread: q[64] (pre-scaled), o[64] accum, online softmax (m, l).
// K/V tiles of 32 keys staged in smem; per-key dot via float4 smem broadcast.
// ============================================================================

#define QB 128   // queries per block
#define KT 32    // keys per tile

__global__ __launch_bounds__(128) void attn_kernel(int B)
{
    const int bh = blockIdx.y;
    const int b  = bh >> 4;       // / NH
    const int h  = bh & 15;       // % NH
    const int q_idx = blockIdx.x * QB + threadIdx.x;

    const float scale = 0.125f;   // 1/sqrt(64)

    __shared__ float Ks[KT][HD];
    __shared__ float Vs[KT][HD];

    // Load and pre-scale q
    float q[HD];
    {
        const float4* qp = reinterpret_cast<const float4*>(
            &g_q[(size_t)(b * S_LEN + q_idx) * E_DIM + h * HD]);
#pragma unroll
        for (int d4 = 0; d4 < 16; ++d4) {
            float4 v = qp[d4];
            q[4 * d4 + 0] = v.x * scale;
            q[4 * d4 + 1] = v.y * scale;
            q[4 * d4 + 2] = v.z * scale;
            q[4 * d4 + 3] = v.w * scale;
        }
    }

    float o[HD];
#pragma unroll
    for (int d = 0; d < HD; ++d) o[d] = 0.0f;
    float m = -INFINITY;
    float l = 0.0f;

    const int lr = threadIdx.x >> 2;       // tile row this thread loads (0..31)
    const int lf = threadIdx.x & 3;        // float4 phase (0..3)

    for (int kt = 0; kt < S_LEN; kt += KT) {
        __syncthreads();
        // Stage K/V tile: 32 rows x 64 floats each
        const size_t base = (size_t)(b * S_LEN + kt) * E_DIM + h * HD;
        const float4* krow = reinterpret_cast<const float4*>(
            &g_k[base + (size_t)lr * E_DIM]);
        const float4* vrow = reinterpret_cast<const float4*>(
            &g_v[base + (size_t)lr * E_DIM]);
        float4* ksm = reinterpret_cast<float4*>(Ks[lr]);
        float4* vsm = reinterpret_cast<float4*>(Vs[lr]);
#pragma unroll
        for (int j = 0; j < 4; ++j) {
            const int f4 = lf + j * 4;     // 0..15
            ksm[f4] = krow[f4];
            vsm[f4] = vrow[f4];
        }
        __syncthreads();

        // Scores for this tile
        float s[KT];
        float tmax = m;
#pragma unroll
        for (int j = 0; j < KT; ++j) {
            const float4* kr = reinterpret_cast<const float4*>(Ks[j]);
            float acc = 0.0f;
#pragma unroll
            for (int d4 = 0; d4 < 16; ++d4) {
                float4 kv = kr[d4];
                acc = fmaf(q[4 * d4 + 0], kv.x, acc);
                acc = fmaf(q[4 * d4 + 1], kv.y, acc);
                acc = fmaf(q[4 * d4 + 2], kv.z, acc);
                acc = fmaf(q[4 * d4 + 3], kv.w, acc);
            }
            s[j] = acc;
            tmax = fmaxf(tmax, acc);
        }

        // Online softmax rescale
        const float corr = __expf(m - tmax);
        m = tmax;
        l *= corr;
#pragma unroll
        for (int d = 0; d < HD; ++d) o[d] *= corr;

#pragma unroll
        for (int j = 0; j < KT; ++j) {
            const float p = __expf(s[j] - m);
            l += p;
            const float4* vr = reinterpret_cast<const float4*>(Vs[j]);
#pragma unroll
            for (int d4 = 0; d4 < 16; ++d4) {
                float4 vv = vr[d4];
                o[4 * d4 + 0] = fmaf(p, vv.x, o[4 * d4 + 0]);
                o[4 * d4 + 1] = fmaf(p, vv.y, o[4 * d4 + 1]);
                o[4 * d4 + 2] = fmaf(p, vv.z, o[4 * d4 + 2]);
                o[4 * d4 + 3] = fmaf(p, vv.w, o[4 * d4 + 3]);
            }
        }
    }

    // Normalize and write back in [B, S, H*D] layout (ready for output GEMM)
    const float inv = 1.0f / l;
    float4* op = reinterpret_cast<float4*>(
        &g_attn[(size_t)(b * S_LEN + q_idx) * E_DIM + h * HD]);
#pragma unroll
    for (int d4 = 0; d4 < 16; ++d4) {
        float4 v;
        v.x = o[4 * d4 + 0] * inv;
        v.y = o[4 * d4 + 1] * inv;
        v.z = o[4 * d4 + 2] * inv;
        v.w = o[4 * d4 + 3] * inv;
        op[d4] = v;
    }
}

// ============================================================================
// Launch
// ============================================================================

extern "C" void kernel_launch(void* const* d_in, const int* in_sizes, int n_in,
                              void* d_out, int out_size)
{
    const float* x  = (const float*)d_in[0];
    const float* Wq = (const float*)d_in[1];
    const float* bq = (const float*)d_in[2];
    const float* Wk = (const float*)d_in[3];
    const float* bk = (const float*)d_in[4];
    const float* Wv = (const float*)d_in[5];
    const float* bv = (const float*)d_in[6];
    const float* Wo = (const float*)d_in[7];
    const float* bo = (const float*)d_in[8];
    float* out = (float*)d_out;

    const int M = in_sizes[0] / E_DIM;   // B*S = 4096
    const int B = M / S_LEN;             // 2

    // 1) Fused QKV projections
    {
        dim3 grid(E_DIM / GBN, M / GBM, 3);   // (8, 32, 3)
        gemm_qkv_kernel<<<grid, 256>>>(x, Wq, bq, Wk, bk, Wv, bv, M);
    }

    // 2) Attention (flash-style, online softmax)
    {
        dim3 grid(S_LEN / QB, B * NH);        // (16, 32)
        attn_kernel<<<grid, 128>>>(B);
    }

    // 3) Output projection
    {
        dim3 grid(E_DIM / GBN, M / GBM);      // (8, 32)
        gemm_out_kernel<<<grid, 256>>>(Wo, bo, out, M);
    }
}

// round 2
// speedup vs baseline: 2.2242x; 2.2242x over previous
#include <cuda_runtime.h>
#include <cuda_bf16.h>
#include <math.h>
#include <stdint.h>

// ============================================================================
// B=2, S=2048, E=1024, H=16, D=64.  M = 4096.
// All matmuls on tensor cores via bf16x2 error-free split (3 MMAs per product):
//   a = a_hi + a_lo (both bf16, exact split), ab ~= ah*bh + ah*bl + al*bh
// Residual ~2^-17 per term -> norm rel_err ~1e-5, far under 1e-3.
// ============================================================================

#define E_DIM 1024
#define NH    16
#define HD    64
#define S_LEN 2048
#define MAX_M 4096
#define NELEM 4194304   // MAX_M * E_DIM
#define WELEM 1048576   // E_DIM * E_DIM

// ---- device scratch (bf16 hi/lo pairs) ----
__device__ __nv_bfloat16 g_xh[NELEM], g_xl[NELEM];
__device__ __nv_bfloat16 g_wh[4 * WELEM], g_wl[4 * WELEM];   // Wq,Wk,Wv,Wo
__device__ __nv_bfloat16 g_qh[NELEM], g_ql[NELEM];
__device__ __nv_bfloat16 g_kh[NELEM], g_kl[NELEM];
__device__ __nv_bfloat16 g_vh[NELEM], g_vl[NELEM];
__device__ __nv_bfloat16 g_ah[NELEM], g_al[NELEM];

// ---- helpers ----
__device__ __forceinline__ void mma_bf16(float c[4],
    uint32_t a0, uint32_t a1, uint32_t a2, uint32_t a3,
    uint32_t b0, uint32_t b1)
{
    asm volatile(
        "mma.sync.aligned.m16n8k16.row.col.f32.bf16.bf16.f32 "
        "{%0,%1,%2,%3}, {%4,%5,%6,%7}, {%8,%9}, {%0,%1,%2,%3};"
        : "+f"(c[0]), "+f"(c[1]), "+f"(c[2]), "+f"(c[3])
        : "r"(a0), "r"(a1), "r"(a2), "r"(a3), "r"(b0), "r"(b1));
}

__device__ __forceinline__ float ex2f(float x) {
    float y;
    asm("ex2.approx.ftz.f32 %0, %1;" : "=f"(y) : "f"(x));
    return y;
}

// split two floats into packed bf16x2 hi and lo words (low half = first arg)
__device__ __forceinline__ void split2(float x, float y,
                                       uint32_t& hw, uint32_t& lw)
{
    __nv_bfloat16 hx = __float2bfloat16_rn(x);
    __nv_bfloat16 hy = __float2bfloat16_rn(y);
    __nv_bfloat16 lx = __float2bfloat16_rn(x - __bfloat162float(hx));
    __nv_bfloat16 ly = __float2bfloat16_rn(y - __bfloat162float(hy));
    __nv_bfloat162 H = __halves2bfloat162(hx, hy);
    __nv_bfloat162 L = __halves2bfloat162(lx, ly);
    hw = *reinterpret_cast<uint32_t*>(&H);
    lw = *reinterpret_cast<uint32_t*>(&L);
}

__device__ __forceinline__ uint32_t pack2(__nv_bfloat16 a, __nv_bfloat16 b) {
    __nv_bfloat162 t = __halves2bfloat162(a, b);
    return *reinterpret_cast<uint32_t*>(&t);
}

// ============================================================================
// Pre-split kernel: x and all 4 weight matrices -> bf16 hi/lo
// ============================================================================
__global__ __launch_bounds__(256) void split_kernel(
    const float* __restrict__ x,
    const float* __restrict__ Wq, const float* __restrict__ Wk,
    const float* __restrict__ Wv, const float* __restrict__ Wo)
{
    int i = blockIdx.x * 256 + threadIdx.x;   // grid sized exactly NELEM + 4*WELEM
    float v;
    __nv_bfloat16 *ph, *pl;
    if (i < NELEM) {
        v = x[i]; ph = g_xh + i; pl = g_xl + i;
    } else {
        int j = i - NELEM;
        int w = j >> 20;
        int off = j & (WELEM - 1);
        const float* W = (w == 0) ? Wq : (w == 1) ? Wk : (w == 2) ? Wv : Wo;
        v = W[off]; ph = g_wh + j; pl = g_wl + j;
    }
    __nv_bfloat16 hi = __float2bfloat16_rn(v);
    __nv_bfloat16 lo = __float2bfloat16_rn(v - __bfloat162float(hi));
    *ph = hi; *pl = lo;
}

// ============================================================================
// Split-bf16 GEMM:  C[m,n] = sum_k A[m,k]*W[n,k] + bias[n]
// A,W given as bf16 hi/lo.  BM=128, BN=128, BK=32, 256 thr (8 warps 4m x 2n),
// warp tile 32x64 via m16n8k16.  SPLIT_OUT: write bf16 hi/lo, else fp32.
// smem rows padded to 36 bf16 (18 words) -> conflict-free fragment loads.
// ============================================================================
#define GPAD 36

template<bool SPLIT_OUT>
__device__ __forceinline__ void gemm_core(
    const __nv_bfloat16* __restrict__ Ah, const __nv_bfloat16* __restrict__ Al,
    const __nv_bfloat16* __restrict__ Wh, const __nv_bfloat16* __restrict__ Wl,
    const float* __restrict__ bias,
    float* __restrict__ outF,
    __nv_bfloat16* __restrict__ Oh, __nv_bfloat16* __restrict__ Ol)
{
    __shared__ __nv_bfloat16 sAh[128 * GPAD], sAl[128 * GPAD];
    __shared__ __nv_bfloat16 sWh[128 * GPAD], sWl[128 * GPAD];

    const int tid  = threadIdx.x;
    const int lane = tid & 31;
    const int wid  = tid >> 5;
    const int wm   = wid & 3;          // 4 warps in m
    const int wn   = wid >> 2;         // 2 warps in n
    const int g    = lane >> 2;
    const int t4   = lane & 3;
    const int bm   = blockIdx.y * 128;
    const int bn   = blockIdx.x * 128;

    float acc[2][8][4];
#pragma unroll
    for (int s = 0; s < 2; ++s)
#pragma unroll
        for (int j = 0; j < 8; ++j)
#pragma unroll
            for (int e = 0; e < 4; ++e) acc[s][j][e] = 0.0f;

    const uint32_t* wAh = reinterpret_cast<const uint32_t*>(sAh);
    const uint32_t* wAl = reinterpret_cast<const uint32_t*>(sAl);
    const uint32_t* wWh = reinterpret_cast<const uint32_t*>(sWh);
    const uint32_t* wWl = reinterpret_cast<const uint32_t*>(sWl);

    for (int kt = 0; kt < E_DIM; kt += 32) {
        __syncthreads();
        // stage: 128 rows x 32 bf16 per array, uint2 (4 bf16) granularity
#pragma unroll
        for (int i = 0; i < 4; ++i) {
            const int idx = tid + i * 256;       // 0..1023
            const int row = idx >> 3;            // 0..127
            const int c   = idx & 7;             // 0..7
            const size_t ga = (size_t)(bm + row) * E_DIM + kt + c * 4;
            const size_t gw = (size_t)(bn + row) * E_DIM + kt + c * 4;
            *reinterpret_cast<uint2*>(&sAh[row * GPAD + c * 4]) =
                *reinterpret_cast<const uint2*>(Ah + ga);
            *reinterpret_cast<uint2*>(&sAl[row * GPAD + c * 4]) =
                *reinterpret_cast<const uint2*>(Al + ga);
            *reinterpret_cast<uint2*>(&sWh[row * GPAD + c * 4]) =
                *reinterpret_cast<const uint2*>(Wh + gw);
            *reinterpret_cast<uint2*>(&sWl[row * GPAD + c * 4]) =
                *reinterpret_cast<const uint2*>(Wl + gw);
        }
        __syncthreads();

#pragma unroll
        for (int kk = 0; kk < 2; ++kk) {
            uint32_t afh[2][4], afl[2][4];
#pragma unroll
            for (int s = 0; s < 2; ++s) {
                const int rb = (wm * 32 + s * 16 + g) * 18 + kk * 8 + t4;
                afh[s][0] = wAh[rb];        afh[s][1] = wAh[rb + 8 * 18];
                afh[s][2] = wAh[rb + 4];    afh[s][3] = wAh[rb + 8 * 18 + 4];
                afl[s][0] = wAl[rb];        afl[s][1] = wAl[rb + 8 * 18];
                afl[s][2] = wAl[rb + 4];    afl[s][3] = wAl[rb + 8 * 18 + 4];
            }
#pragma unroll
            for (int j = 0; j < 8; ++j) {
                const int nb = (wn * 64 + j * 8 + g) * 18 + kk * 8 + t4;
                const uint32_t bh0 = wWh[nb], bh1 = wWh[nb + 4];
                const uint32_t bl0 = wWl[nb], bl1 = wWl[nb + 4];
#pragma unroll
                for (int s = 0; s < 2; ++s) {
                    mma_bf16(acc[s][j], afh[s][0], afh[s][1], afh[s][2], afh[s][3], bh0, bh1);
                    mma_bf16(acc[s][j], afh[s][0], afh[s][1], afh[s][2], afh[s][3], bl0, bl1);
                    mma_bf16(acc[s][j], afl[s][0], afl[s][1], afl[s][2], afl[s][3], bh0, bh1);
                }
            }
        }
    }

    // epilogue
#pragma unroll
    for (int j = 0; j < 8; ++j) {
        const int col = bn + wn * 64 + j * 8 + 2 * t4;
        const float b0 = bias[col], b1 = bias[col + 1];
#pragma unroll
        for (int s = 0; s < 2; ++s) {
            const int r0 = bm + wm * 32 + s * 16 + g;
            const float v0 = acc[s][j][0] + b0, v1 = acc[s][j][1] + b1;
            const float v2 = acc[s][j][2] + b0, v3 = acc[s][j][3] + b1;
            if (SPLIT_OUT) {
                uint32_t hw, lw;
                const size_t w0 = ((size_t)r0 * E_DIM + col) >> 1;
                split2(v0, v1, hw, lw);
                reinterpret_cast<uint32_t*>(Oh)[w0] = hw;
                reinterpret_cast<uint32_t*>(Ol)[w0] = lw;
                const size_t w1 = ((size_t)(r0 + 8) * E_DIM + col) >> 1;
                split2(v2, v3, hw, lw);
                reinterpret_cast<uint32_t*>(Oh)[w1] = hw;
                reinterpret_cast<uint32_t*>(Ol)[w1] = lw;
            } else {
                float2 p0; p0.x = v0; p0.y = v1;
                float2 p1; p1.x = v2; p1.y = v3;
                *reinterpret_cast<float2*>(outF + (size_t)r0 * E_DIM + col) = p0;
                *reinterpret_cast<float2*>(outF + (size_t)(r0 + 8) * E_DIM + col) = p1;
            }
        }
    }
}

__global__ __launch_bounds__(256, 2) void qkv_kernel(
    const float* __restrict__ bq, const float* __restrict__ bk,
    const float* __restrict__ bv)
{
    const int z = blockIdx.z;
    const __nv_bfloat16* Wh = g_wh + (size_t)z * WELEM;
    const __nv_bfloat16* Wl = g_wl + (size_t)z * WELEM;
    const float* bias = (z == 0) ? bq : (z == 1) ? bk : bv;
    __nv_bfloat16* Oh = (z == 0) ? g_qh : (z == 1) ? g_kh : g_vh;
    __nv_bfloat16* Ol = (z == 0) ? g_ql : (z == 1) ? g_kl : g_vl;
    gemm_core<true>(g_xh, g_xl, Wh, Wl, bias, nullptr, Oh, Ol);
}

__global__ __launch_bounds__(256, 2) void outproj_kernel(
    const float* __restrict__ bo, float* __restrict__ out)
{
    gemm_core<false>(g_ah, g_al, g_wh + (size_t)3 * WELEM, g_wl + (size_t)3 * WELEM,
                     bo, out, nullptr, nullptr);
}

// ============================================================================
// Tensor-core flash attention.
// Block: 128 thr (4 warps), one (b,h), Q tile 64 rows (16/warp), K tiles of 64.
// QK^T and PV on mma.m16n8k16 with bf16x2 split (3 mma each).
// P fragments built in registers (C-fragment == A-fragment layout identity).
// smem rows padded to 72 bf16 (36 words).
// ============================================================================
#define APAD 72

__global__ __launch_bounds__(128) void attn_kernel()
{
    __shared__ __nv_bfloat16 sKh[64 * APAD], sKl[64 * APAD];
    __shared__ __nv_bfloat16 sVh[64 * APAD], sVl[64 * APAD];

    const int tid  = threadIdx.x;
    const int lane = tid & 31;
    const int wid  = tid >> 5;
    const int g    = lane >> 2;
    const int t4   = lane & 3;

    const int bh = blockIdx.y;
    const int b  = bh >> 4;
    const int h  = bh & 15;
    const int q0 = blockIdx.x * 64 + wid * 16;
    const size_t qrow0 = (size_t)(b * S_LEN + q0);

    const float cs = 0.18033688011112042f;   // (1/8) * log2(e)

    // Q fragments (hi/lo), 4 k-steps over D=64
    uint32_t qfh[4][4], qfl[4][4];
#pragma unroll
    for (int kk = 0; kk < 4; ++kk) {
        const size_t i0 = (qrow0 + g) * E_DIM + h * HD + kk * 16 + 2 * t4;
        const size_t i1 = (qrow0 + g + 8) * E_DIM + h * HD + kk * 16 + 2 * t4;
        qfh[kk][0] = *reinterpret_cast<const uint32_t*>(g_qh + i0);
        qfh[kk][1] = *reinterpret_cast<const uint32_t*>(g_qh + i1);
        qfh[kk][2] = *reinterpret_cast<const uint32_t*>(g_qh + i0 + 8);
        qfh[kk][3] = *reinterpret_cast<const uint32_t*>(g_qh + i1 + 8);
        qfl[kk][0] = *reinterpret_cast<const uint32_t*>(g_ql + i0);
        qfl[kk][1] = *reinterpret_cast<const uint32_t*>(g_ql + i1);
        qfl[kk][2] = *reinterpret_cast<const uint32_t*>(g_ql + i0 + 8);
        qfl[kk][3] = *reinterpret_cast<const uint32_t*>(g_ql + i1 + 8);
    }

    float oacc[8][4];
#pragma unroll
    for (int jd = 0; jd < 8; ++jd)
#pragma unroll
        for (int e = 0; e < 4; ++e) oacc[jd][e] = 0.0f;
    float m0 = -INFINITY, m1 = -INFINITY, l0 = 0.0f, l1 = 0.0f;

    const uint32_t* wKh = reinterpret_cast<const uint32_t*>(sKh);
    const uint32_t* wKl = reinterpret_cast<const uint32_t*>(sKl);

    for (int kt = 0; kt < S_LEN / 64; ++kt) {
        __syncthreads();
        // stage K/V hi/lo tiles: 64 rows x 64 bf16 each
#pragma unroll
        for (int i = 0; i < 8; ++i) {
            const int idx = tid + i * 128;       // 0..1023
            const int row = idx >> 4;            // 0..63
            const int c   = idx & 15;            // 0..15
            const size_t src = (size_t)(b * S_LEN + kt * 64 + row) * E_DIM
                             + h * HD + c * 4;
            *reinterpret_cast<uint2*>(&sKh[row * APAD + c * 4]) =
                *reinterpret_cast<const uint2*>(g_kh + src);
            *reinterpret_cast<uint2*>(&sKl[row * APAD + c * 4]) =
                *reinterpret_cast<const uint2*>(g_kl + src);
            *reinterpret_cast<uint2*>(&sVh[row * APAD + c * 4]) =
                *reinterpret_cast<const uint2*>(g_vh + src);
            *reinterpret_cast<uint2*>(&sVl[row * APAD + c * 4]) =
                *reinterpret_cast<const uint2*>(g_vl + src);
        }
        __syncthreads();

        // ---- QK^T: S[16 x 64] ----
        float sacc[8][4];
#pragma unroll
        for (int j = 0; j < 8; ++j)
#pragma unroll
            for (int e = 0; e < 4; ++e) sacc[j][e] = 0.0f;

#pragma unroll
        for (int j = 0; j < 8; ++j) {
#pragma unroll
            for (int kk = 0; kk < 4; ++kk) {
                const int nb = (j * 8 + g) * 36 + kk * 8 + t4;
                const uint32_t kb0 = wKh[nb], kb1 = wKh[nb + 4];
                const uint32_t kl0 = wKl[nb], kl1 = wKl[nb + 4];
                mma_bf16(sacc[j], qfh[kk][0], qfh[kk][1], qfh[kk][2], qfh[kk][3], kb0, kb1);
                mma_bf16(sacc[j], qfh[kk][0], qfh[kk][1], qfh[kk][2], qfh[kk][3], kl0, kl1);
                mma_bf16(sacc[j], qfl[kk][0], qfl[kk][1], qfl[kk][2], qfl[kk][3], kb0, kb1);
            }
        }

        // ---- online softmax (scores scaled by cs in exp domain) ----
        float nm0 = m0, nm1 = m1;
#pragma unroll
        for (int j = 0; j < 8; ++j) {
            nm0 = fmaxf(nm0, fmaxf(sacc[j][0], sacc[j][1]));
            nm1 = fmaxf(nm1, fmaxf(sacc[j][2], sacc[j][3]));
        }
        nm0 = fmaxf(nm0, __shfl_xor_sync(0xffffffffu, nm0, 1));
        nm0 = fmaxf(nm0, __shfl_xor_sync(0xffffffffu, nm0, 2));
        nm1 = fmaxf(nm1, __shfl_xor_sync(0xffffffffu, nm1, 1));
        nm1 = fmaxf(nm1, __shfl_xor_sync(0xffffffffu, nm1, 2));

        const float c0 = ex2f((m0 - nm0) * cs);
        const float c1 = ex2f((m1 - nm1) * cs);
        m0 = nm0; m1 = nm1;
        l0 *= c0;  l1 *= c1;

#pragma unroll
        for (int j = 0; j < 8; ++j) {
            const float p0 = ex2f((sacc[j][0] - m0) * cs);
            const float p1 = ex2f((sacc[j][1] - m0) * cs);
            const float p2 = ex2f((sacc[j][2] - m1) * cs);
            const float p3 = ex2f((sacc[j][3] - m1) * cs);
            l0 += p0 + p1;
            l1 += p2 + p3;
            sacc[j][0] = p0; sacc[j][1] = p1; sacc[j][2] = p2; sacc[j][3] = p3;
        }
#pragma unroll
        for (int jd = 0; jd < 8; ++jd) {
            oacc[jd][0] *= c0; oacc[jd][1] *= c0;
            oacc[jd][2] *= c1; oacc[jd][3] *= c1;
        }

        // ---- PV: O += P[16 x 64] @ V[64 x 64] ----
#pragma unroll
        for (int kk = 0; kk < 4; ++kk) {
            uint32_t pah[4], pal[4];
            split2(sacc[2 * kk][0],     sacc[2 * kk][1],     pah[0], pal[0]);
            split2(sacc[2 * kk][2],     sacc[2 * kk][3],     pah[1], pal[1]);
            split2(sacc[2 * kk + 1][0], sacc[2 * kk + 1][1], pah[2], pal[2]);
            split2(sacc[2 * kk + 1][2], sacc[2 * kk + 1][3], pah[3], pal[3]);
#pragma unroll
            for (int jd = 0; jd < 8; ++jd) {
                const int d  = jd * 8 + g;
                const int k0 = kk * 16 + 2 * t4;
                const uint32_t vh0 = pack2(sVh[k0 * APAD + d],       sVh[(k0 + 1) * APAD + d]);
                const uint32_t vh1 = pack2(sVh[(k0 + 8) * APAD + d], sVh[(k0 + 9) * APAD + d]);
                const uint32_t vl0 = pack2(sVl[k0 * APAD + d],       sVl[(k0 + 1) * APAD + d]);
                const uint32_t vl1 = pack2(sVl[(k0 + 8) * APAD + d], sVl[(k0 + 9) * APAD + d]);
                mma_bf16(oacc[jd], pah[0], pah[1], pah[2], pah[3], vh0, vh1);
                mma_bf16(oacc[jd], pah[0], pah[1], pah[2], pah[3], vl0, vl1);
                mma_bf16(oacc[jd], pal[0], pal[1], pal[2], pal[3], vh0, vh1);
            }
        }
    }

    // ---- finalize: quad-reduce l, normalize, split-store ----
    l0 += __shfl_xor_sync(0xffffffffu, l0, 1);
    l0 += __shfl_xor_sync(0xffffffffu, l0, 2);
    l1 += __shfl_xor_sync(0xffffffffu, l1, 1);
    l1 += __shfl_xor_sync(0xffffffffu, l1, 2);
    const float inv0 = 1.0f / l0;
    const float inv1 = 1.0f / l1;

#pragma unroll
    for (int jd = 0; jd < 8; ++jd) {
        const int col = h * HD + jd * 8 + 2 * t4;
        const size_t w0 = ((qrow0 + g) * E_DIM + col) >> 1;
        const size_t w1 = ((qrow0 + g + 8) * E_DIM + col) >> 1;
        uint32_t hw, lw;
        split2(oacc[jd][0] * inv0, oacc[jd][1] * inv0, hw, lw);
        reinterpret_cast<uint32_t*>(g_ah)[w0] = hw;
        reinterpret_cast<uint32_t*>(g_al)[w0] = lw;
        split2(oacc[jd][2] * inv1, oacc[jd][3] * inv1, hw, lw);
        reinterpret_cast<uint32_t*>(g_ah)[w1] = hw;
        reinterpret_cast<uint32_t*>(g_al)[w1] = lw;
    }
}

// ============================================================================
// Launch
// ============================================================================
extern "C" void kernel_launch(void* const* d_in, const int* in_sizes, int n_in,
                              void* d_out, int out_size)
{
    const float* x  = (const float*)d_in[0];
    const float* Wq = (const float*)d_in[1];
    const float* bq = (const float*)d_in[2];
    const float* Wk = (const float*)d_in[3];
    const float* bk = (const float*)d_in[4];
    const float* Wv = (const float*)d_in[5];
    const float* bv = (const float*)d_in[6];
    const float* Wo = (const float*)d_in[7];
    const float* bo = (const float*)d_in[8];
    float* out = (float*)d_out;

    // 0) split x and weights into bf16 hi/lo
    {
        const int total = NELEM + 4 * WELEM;      // 8,388,608
        split_kernel<<<total / 256, 256>>>(x, Wq, Wk, Wv, Wo);
    }
    // 1) fused QKV projections (split-bf16 tensor GEMM, split bf16 output)
    {
        dim3 grid(E_DIM / 128, MAX_M / 128, 3);   // (8, 32, 3)
        qkv_kernel<<<grid, 256>>>(bq, bk, bv);
    }
    // 2) tensor-core flash attention
    {
        dim3 grid(S_LEN / 64, 2 * NH);            // (32, 32)
        attn_kernel<<<grid, 128>>>();
    }
    // 3) output projection (fp32 out)
    {
        dim3 grid(E_DIM / 128, MAX_M / 128);      // (8, 32)
        outproj_kernel<<<grid, 256>>>(bo, out);
    }
}

// round 3
// speedup vs baseline: 3.2331x; 1.4536x over previous
#include <cuda_runtime.h>
#include <cuda_bf16.h>
#include <math.h>
#include <stdint.h>

// ============================================================================
// B=2, S=2048, E=1024, H=16, D=64.  M = 4096.
// All matmuls on tensor cores via bf16x2 error-free split (3 MMAs / product).
// This round: ldmatrix fragment loads + cp.async double buffering everywhere.
// ============================================================================

#define E_DIM 1024
#define NH    16
#define HD    64
#define S_LEN 2048
#define MAX_M 4096
#define NELEM 4194304   // MAX_M * E_DIM
#define WELEM 1048576   // E_DIM * E_DIM

// ---- device scratch (bf16 hi/lo pairs) ----
__device__ __nv_bfloat16 g_xh[NELEM], g_xl[NELEM];
__device__ __nv_bfloat16 g_wh[4 * WELEM], g_wl[4 * WELEM];   // Wq,Wk,Wv,Wo
__device__ __nv_bfloat16 g_qh[NELEM], g_ql[NELEM];
__device__ __nv_bfloat16 g_kh[NELEM], g_kl[NELEM];
__device__ __nv_bfloat16 g_vh[NELEM], g_vl[NELEM];
__device__ __nv_bfloat16 g_ah[NELEM], g_al[NELEM];

// ---- helpers ----
__device__ __forceinline__ void mma_bf16(float c[4],
    uint32_t a0, uint32_t a1, uint32_t a2, uint32_t a3,
    uint32_t b0, uint32_t b1)
{
    asm volatile(
        "mma.sync.aligned.m16n8k16.row.col.f32.bf16.bf16.f32 "
        "{%0,%1,%2,%3}, {%4,%5,%6,%7}, {%8,%9}, {%0,%1,%2,%3};"
        : "+f"(c[0]), "+f"(c[1]), "+f"(c[2]), "+f"(c[3])
        : "r"(a0), "r"(a1), "r"(a2), "r"(a3), "r"(b0), "r"(b1));
}

__device__ __forceinline__ float ex2f(float x) {
    float y;
    asm("ex2.approx.ftz.f32 %0, %1;" : "=f"(y) : "f"(x));
    return y;
}

__device__ __forceinline__ void split2(float x, float y,
                                       uint32_t& hw, uint32_t& lw)
{
    __nv_bfloat16 hx = __float2bfloat16_rn(x);
    __nv_bfloat16 hy = __float2bfloat16_rn(y);
    __nv_bfloat16 lx = __float2bfloat16_rn(x - __bfloat162float(hx));
    __nv_bfloat16 ly = __float2bfloat16_rn(y - __bfloat162float(hy));
    __nv_bfloat162 H = __halves2bfloat162(hx, hy);
    __nv_bfloat162 L = __halves2bfloat162(lx, ly);
    hw = *reinterpret_cast<uint32_t*>(&H);
    lw = *reinterpret_cast<uint32_t*>(&L);
}

__device__ __forceinline__ uint32_t smem_u32(const void* p) {
    return (uint32_t)__cvta_generic_to_shared(p);
}

__device__ __forceinline__ void ldsm4(uint32_t& r0, uint32_t& r1,
                                      uint32_t& r2, uint32_t& r3, uint32_t a) {
    asm volatile("ldmatrix.sync.aligned.m8n8.x4.shared.b16 {%0,%1,%2,%3}, [%4];"
        : "=r"(r0), "=r"(r1), "=r"(r2), "=r"(r3) : "r"(a));
}

__device__ __forceinline__ void ldsm4t(uint32_t& r0, uint32_t& r1,
                                       uint32_t& r2, uint32_t& r3, uint32_t a) {
    asm volatile("ldmatrix.sync.aligned.m8n8.x4.trans.shared.b16 {%0,%1,%2,%3}, [%4];"
        : "=r"(r0), "=r"(r1), "=r"(r2), "=r"(r3) : "r"(a));
}

__device__ __forceinline__ void cp16(uint32_t dst, const void* src) {
    asm volatile("cp.async.cg.shared.global [%0], [%1], 16;"
        :: "r"(dst), "l"(src));
}
#define CP_COMMIT() asm volatile("cp.async.commit_group;")
#define CP_WAIT1()  asm volatile("cp.async.wait_group 1;")
#define CP_WAIT0()  asm volatile("cp.async.wait_group 0;")

// ============================================================================
// Pre-split kernel: x and all 4 weight matrices -> bf16 hi/lo
// ============================================================================
__global__ __launch_bounds__(256) void split_kernel(
    const float* __restrict__ x,
    const float* __restrict__ Wq, const float* __restrict__ Wk,
    const float* __restrict__ Wv, const float* __restrict__ Wo)
{
    int i = blockIdx.x * 256 + threadIdx.x;
    float v;
    __nv_bfloat16 *ph, *pl;
    if (i < NELEM) {
        v = x[i]; ph = g_xh + i; pl = g_xl + i;
    } else {
        int j = i - NELEM;
        int w = j >> 20;
        int off = j & (WELEM - 1);
        const float* W = (w == 0) ? Wq : (w == 1) ? Wk : (w == 2) ? Wv : Wo;
        v = W[off]; ph = g_wh + j; pl = g_wl + j;
    }
    __nv_bfloat16 hi = __float2bfloat16_rn(v);
    __nv_bfloat16 lo = __float2bfloat16_rn(v - __bfloat162float(hi));
    *ph = hi; *pl = lo;
}

// ============================================================================
// Split-bf16 GEMM:  C[m,n] = sum_k A[m,k]*W[n,k] + bias[n]
// BM=128, BN=128, BK=32, 256 thr (4m x 2n warps, warp tile 32x64).
// cp.async 2-stage double buffer; ldmatrix.x4 fragment loads.
// smem row stride 40 bf16 (80B, 16B-aligned, conflict-free for ldmatrix).
// ============================================================================
#define GROW 40
#define GT   (128 * GROW)     // elements per array per stage

template<bool SPLIT_OUT>
__device__ __forceinline__ void gemm_core(
    const __nv_bfloat16* __restrict__ Ah, const __nv_bfloat16* __restrict__ Al,
    const __nv_bfloat16* __restrict__ Wh, const __nv_bfloat16* __restrict__ Wl,
    const float* __restrict__ bias,
    float* __restrict__ outF,
    __nv_bfloat16* __restrict__ Oh, __nv_bfloat16* __restrict__ Ol)
{
    extern __shared__ __nv_bfloat16 sm[];
    const int tid  = threadIdx.x;
    const int lane = tid & 31;
    const int wid  = tid >> 5;
    const int wm   = wid & 3;
    const int wn   = wid >> 2;
    const int g    = lane >> 2;
    const int t4   = lane & 3;
    const int bm   = blockIdx.y * 128;
    const int bn   = blockIdx.x * 128;

    float acc[2][8][4];
#pragma unroll
    for (int s = 0; s < 2; ++s)
#pragma unroll
        for (int j = 0; j < 8; ++j)
#pragma unroll
            for (int e = 0; e < 4; ++e) acc[s][j][e] = 0.0f;

    auto load_stage = [&](int s, int kt) {
#pragma unroll
        for (int i = 0; i < 8; ++i) {
            const int a   = i >> 1;                 // 0:Ah 1:Al 2:Wh 3:Wl
            const int c   = (i & 1) * 256 + tid;    // [0,512)
            const int row = c >> 2;
            const int col = (c & 3) * 8;
            const __nv_bfloat16* base = (a == 0) ? Ah : (a == 1) ? Al
                                      : (a == 2) ? Wh : Wl;
            const int rb = (a < 2) ? bm : bn;
            cp16(smem_u32(sm + (s * 4 + a) * GT + row * GROW + col),
                 base + (size_t)(rb + row) * E_DIM + kt + col);
        }
    };

    load_stage(0, 0);
    CP_COMMIT();

    const int NT = E_DIM / 32;
    for (int t = 0; t < NT; ++t) {
        const int s = t & 1;
        if (t + 1 < NT) {
            load_stage(s ^ 1, (t + 1) * 32);
            CP_COMMIT();
            CP_WAIT1();
        } else {
            CP_WAIT0();
        }
        __syncthreads();

        const uint32_t bAh = smem_u32(sm + (s * 4 + 0) * GT);
        const uint32_t bAl = smem_u32(sm + (s * 4 + 1) * GT);
        const uint32_t bWh = smem_u32(sm + (s * 4 + 2) * GT);
        const uint32_t bWl = smem_u32(sm + (s * 4 + 3) * GT);

#pragma unroll
        for (int kk = 0; kk < 2; ++kk) {
            uint32_t ah[2][4], al[2][4];
            const int ka = kk * 16 + (lane >> 4) * 8;
#pragma unroll
            for (int ss = 0; ss < 2; ++ss) {
                const int m = wm * 32 + ss * 16 + (lane & 15);
                const uint32_t off = (uint32_t)(m * GROW + ka) * 2;
                ldsm4(ah[ss][0], ah[ss][1], ah[ss][2], ah[ss][3], bAh + off);
                ldsm4(al[ss][0], al[ss][1], al[ss][2], al[ss][3], bAl + off);
            }
            const int kb  = kk * 16 + ((lane >> 3) & 1) * 8;
            const int nb0 = (lane & 7) + ((lane >> 4) << 3);
#pragma unroll
            for (int jp = 0; jp < 4; ++jp) {
                const int n = wn * 64 + jp * 16 + nb0;
                const uint32_t off = (uint32_t)(n * GROW + kb) * 2;
                uint32_t bh[4], bl[4];
                ldsm4(bh[0], bh[1], bh[2], bh[3], bWh + off);
                ldsm4(bl[0], bl[1], bl[2], bl[3], bWl + off);
#pragma unroll
                for (int ss = 0; ss < 2; ++ss) {
                    mma_bf16(acc[ss][2*jp],   ah[ss][0],ah[ss][1],ah[ss][2],ah[ss][3], bh[0],bh[1]);
                    mma_bf16(acc[ss][2*jp],   ah[ss][0],ah[ss][1],ah[ss][2],ah[ss][3], bl[0],bl[1]);
                    mma_bf16(acc[ss][2*jp],   al[ss][0],al[ss][1],al[ss][2],al[ss][3], bh[0],bh[1]);
                    mma_bf16(acc[ss][2*jp+1], ah[ss][0],ah[ss][1],ah[ss][2],ah[ss][3], bh[2],bh[3]);
                    mma_bf16(acc[ss][2*jp+1], ah[ss][0],ah[ss][1],ah[ss][2],ah[ss][3], bl[2],bl[3]);
                    mma_bf16(acc[ss][2*jp+1], al[ss][0],al[ss][1],al[ss][2],al[ss][3], bh[2],bh[3]);
                }
            }
        }
        __syncthreads();
    }

    // epilogue
#pragma unroll
    for (int j = 0; j < 8; ++j) {
        const int col = bn + wn * 64 + j * 8 + 2 * t4;
        const float b0 = bias[col], b1 = bias[col + 1];
#pragma unroll
        for (int ss = 0; ss < 2; ++ss) {
            const int r0 = bm + wm * 32 + ss * 16 + g;
            const float v0 = acc[ss][j][0] + b0, v1 = acc[ss][j][1] + b1;
            const float v2 = acc[ss][j][2] + b0, v3 = acc[ss][j][3] + b1;
            if (SPLIT_OUT) {
                uint32_t hw, lw;
                const size_t w0 = ((size_t)r0 * E_DIM + col) >> 1;
                split2(v0, v1, hw, lw);
                reinterpret_cast<uint32_t*>(Oh)[w0] = hw;
                reinterpret_cast<uint32_t*>(Ol)[w0] = lw;
                const size_t w1 = ((size_t)(r0 + 8) * E_DIM + col) >> 1;
                split2(v2, v3, hw, lw);
                reinterpret_cast<uint32_t*>(Oh)[w1] = hw;
                reinterpret_cast<uint32_t*>(Ol)[w1] = lw;
            } else {
                float2 p0; p0.x = v0; p0.y = v1;
                float2 p1; p1.x = v2; p1.y = v3;
                *reinterpret_cast<float2*>(outF + (size_t)r0 * E_DIM + col) = p0;
                *reinterpret_cast<float2*>(outF + (size_t)(r0 + 8) * E_DIM + col) = p1;
            }
        }
    }
}

__global__ __launch_bounds__(256, 2) void qkv_kernel(
    const float* __restrict__ bq, const float* __restrict__ bk,
    const float* __restrict__ bv)
{
    const int z = blockIdx.z;
    const __nv_bfloat16* Wh = g_wh + (size_t)z * WELEM;
    const __nv_bfloat16* Wl = g_wl + (size_t)z * WELEM;
    const float* bias = (z == 0) ? bq : (z == 1) ? bk : bv;
    __nv_bfloat16* Oh = (z == 0) ? g_qh : (z == 1) ? g_kh : g_vh;
    __nv_bfloat16* Ol = (z == 0) ? g_ql : (z == 1) ? g_kl : g_vl;
    gemm_core<true>(g_xh, g_xl, Wh, Wl, bias, nullptr, Oh, Ol);
}

__global__ __launch_bounds__(256, 2) void outproj_kernel(
    const float* __restrict__ bo, float* __restrict__ out)
{
    gemm_core<false>(g_ah, g_al, g_wh + (size_t)3 * WELEM, g_wl + (size_t)3 * WELEM,
                     bo, out, nullptr, nullptr);
}

// ============================================================================
// Tensor-core flash attention (128 thr, 4 warps, Q tile 64, K tiles of 64).
// cp.async double-buffered K/V hi/lo; ldmatrix for K; ldmatrix.trans for V.
// smem row stride 72 bf16 (144B, 16B-aligned, conflict-free).
// ============================================================================
#define APAD 72
#define AT   (64 * APAD)

__global__ __launch_bounds__(128) void attn_kernel()
{
    extern __shared__ __nv_bfloat16 sm[];
    const int tid  = threadIdx.x;
    const int lane = tid & 31;
    const int wid  = tid >> 5;
    const int g    = lane >> 2;
    const int t4   = lane & 3;

    const int bh = blockIdx.y;
    const int b  = bh >> 4;
    const int h  = bh & 15;
    const int q0 = blockIdx.x * 64 + wid * 16;
    const size_t qrow0 = (size_t)(b * S_LEN + q0);

    const float cs = 0.18033688011112042f;   // (1/8) * log2(e)

    // Q fragments (hi/lo), 4 k-steps over D=64 (from gmem, one-time)
    uint32_t qfh[4][4], qfl[4][4];
#pragma unroll
    for (int kk = 0; kk < 4; ++kk) {
        const size_t i0 = (qrow0 + g) * E_DIM + h * HD + kk * 16 + 2 * t4;
        const size_t i1 = (qrow0 + g + 8) * E_DIM + h * HD + kk * 16 + 2 * t4;
        qfh[kk][0] = *reinterpret_cast<const uint32_t*>(g_qh + i0);
        qfh[kk][1] = *reinterpret_cast<const uint32_t*>(g_qh + i1);
        qfh[kk][2] = *reinterpret_cast<const uint32_t*>(g_qh + i0 + 8);
        qfh[kk][3] = *reinterpret_cast<const uint32_t*>(g_qh + i1 + 8);
        qfl[kk][0] = *reinterpret_cast<const uint32_t*>(g_ql + i0);
        qfl[kk][1] = *reinterpret_cast<const uint32_t*>(g_ql + i1);
        qfl[kk][2] = *reinterpret_cast<const uint32_t*>(g_ql + i0 + 8);
        qfl[kk][3] = *reinterpret_cast<const uint32_t*>(g_ql + i1 + 8);
    }

    float oacc[8][4];
#pragma unroll
    for (int jd = 0; jd < 8; ++jd)
#pragma unroll
        for (int e = 0; e < 4; ++e) oacc[jd][e] = 0.0f;
    float m0 = -INFINITY, m1 = -INFINITY, l0 = 0.0f, l1 = 0.0f;

    auto load_stage = [&](int s, int kt) {
#pragma unroll
        for (int i = 0; i < 16; ++i) {
            const int a   = i >> 2;                 // 0:Kh 1:Kl 2:Vh 3:Vl
            const int c   = (i & 3) * 128 + tid;    // [0,512)
            const int row = c >> 3;
            const int col = (c & 7) * 8;
            const __nv_bfloat16* base = (a == 0) ? g_kh : (a == 1) ? g_kl
                                      : (a == 2) ? g_vh : g_vl;
            cp16(smem_u32(sm + (s * 4 + a) * AT + row * APAD + col),
                 base + (size_t)(b * S_LEN + kt * 64 + row) * E_DIM + h * HD + col);
        }
    };

    load_stage(0, 0);
    CP_COMMIT();

    const int NT = S_LEN / 64;
    for (int t = 0; t < NT; ++t) {
        const int s = t & 1;
        if (t + 1 < NT) {
            load_stage(s ^ 1, t + 1);
            CP_COMMIT();
            CP_WAIT1();
        } else {
            CP_WAIT0();
        }
        __syncthreads();

        const uint32_t bKh = smem_u32(sm + (s * 4 + 0) * AT);
        const uint32_t bKl = smem_u32(sm + (s * 4 + 1) * AT);
        const uint32_t bVh = smem_u32(sm + (s * 4 + 2) * AT);
        const uint32_t bVl = smem_u32(sm + (s * 4 + 3) * AT);

        // ---- QK^T: S[16 x 64] ----
        float sacc[8][4];
#pragma unroll
        for (int j = 0; j < 8; ++j)
#pragma unroll
            for (int e = 0; e < 4; ++e) sacc[j][e] = 0.0f;

        const int nb0 = (lane & 7) + ((lane >> 4) << 3);
        const int kb0 = ((lane >> 3) & 1) * 8;
#pragma unroll
        for (int jp = 0; jp < 4; ++jp) {
            const int n = jp * 16 + nb0;
#pragma unroll
            for (int kk = 0; kk < 4; ++kk) {
                const uint32_t off = (uint32_t)(n * APAD + kk * 16 + kb0) * 2;
                uint32_t kh[4], kl[4];
                ldsm4(kh[0], kh[1], kh[2], kh[3], bKh + off);
                ldsm4(kl[0], kl[1], kl[2], kl[3], bKl + off);
                mma_bf16(sacc[2*jp],   qfh[kk][0],qfh[kk][1],qfh[kk][2],qfh[kk][3], kh[0],kh[1]);
                mma_bf16(sacc[2*jp],   qfh[kk][0],qfh[kk][1],qfh[kk][2],qfh[kk][3], kl[0],kl[1]);
                mma_bf16(sacc[2*jp],   qfl[kk][0],qfl[kk][1],qfl[kk][2],qfl[kk][3], kh[0],kh[1]);
                mma_bf16(sacc[2*jp+1], qfh[kk][0],qfh[kk][1],qfh[kk][2],qfh[kk][3], kh[2],kh[3]);
                mma_bf16(sacc[2*jp+1], qfh[kk][0],qfh[kk][1],qfh[kk][2],qfh[kk][3], kl[2],kl[3]);
                mma_bf16(sacc[2*jp+1], qfl[kk][0],qfl[kk][1],qfl[kk][2],qfl[kk][3], kh[2],kh[3]);
            }
        }

        // ---- online softmax ----
        float nm0 = m0, nm1 = m1;
#pragma unroll
        for (int j = 0; j < 8; ++j) {
            nm0 = fmaxf(nm0, fmaxf(sacc[j][0], sacc[j][1]));
            nm1 = fmaxf(nm1, fmaxf(sacc[j][2], sacc[j][3]));
        }
        nm0 = fmaxf(nm0, __shfl_xor_sync(0xffffffffu, nm0, 1));
        nm0 = fmaxf(nm0, __shfl_xor_sync(0xffffffffu, nm0, 2));
        nm1 = fmaxf(nm1, __shfl_xor_sync(0xffffffffu, nm1, 1));
        nm1 = fmaxf(nm1, __shfl_xor_sync(0xffffffffu, nm1, 2));

        const float c0 = ex2f((m0 - nm0) * cs);
        const float c1 = ex2f((m1 - nm1) * cs);
        m0 = nm0; m1 = nm1;
        l0 *= c0;  l1 *= c1;

#pragma unroll
        for (int j = 0; j < 8; ++j) {
            const float p0 = ex2f((sacc[j][0] - m0) * cs);
            const float p1 = ex2f((sacc[j][1] - m0) * cs);
            const float p2 = ex2f((sacc[j][2] - m1) * cs);
            const float p3 = ex2f((sacc[j][3] - m1) * cs);
            l0 += p0 + p1;
            l1 += p2 + p3;
            sacc[j][0] = p0; sacc[j][1] = p1; sacc[j][2] = p2; sacc[j][3] = p3;
        }
#pragma unroll
        for (int jd = 0; jd < 8; ++jd) {
            oacc[jd][0] *= c0; oacc[jd][1] *= c0;
            oacc[jd][2] *= c1; oacc[jd][3] *= c1;
        }

        // ---- PV: O += P[16 x 64] @ V[64 x 64] ----
        const int krb = ((lane >> 3) & 1) * 8 + (lane & 7);
        const int dcb = (lane >> 4) * 8;
#pragma unroll
        for (int kk = 0; kk < 4; ++kk) {
            uint32_t pah[4], pal[4];
            split2(sacc[2*kk][0],   sacc[2*kk][1],   pah[0], pal[0]);
            split2(sacc[2*kk][2],   sacc[2*kk][3],   pah[1], pal[1]);
            split2(sacc[2*kk+1][0], sacc[2*kk+1][1], pah[2], pal[2]);
            split2(sacc[2*kk+1][2], sacc[2*kk+1][3], pah[3], pal[3]);
            const int kr = kk * 16 + krb;
#pragma unroll
            for (int jdp = 0; jdp < 4; ++jdp) {
                const int dc = jdp * 16 + dcb;
                const uint32_t off = (uint32_t)(kr * APAD + dc) * 2;
                uint32_t vh[4], vl[4];
                ldsm4t(vh[0], vh[1], vh[2], vh[3], bVh + off);
                ldsm4t(vl[0], vl[1], vl[2], vl[3], bVl + off);
                mma_bf16(oacc[2*jdp],   pah[0],pah[1],pah[2],pah[3], vh[0],vh[1]);
                mma_bf16(oacc[2*jdp],   pah[0],pah[1],pah[2],pah[3], vl[0],vl[1]);
                mma_bf16(oacc[2*jdp],   pal[0],pal[1],pal[2],pal[3], vh[0],vh[1]);
                mma_bf16(oacc[2*jdp+1], pah[0],pah[1],pah[2],pah[3], vh[2],vh[3]);
                mma_bf16(oacc[2*jdp+1], pah[0],pah[1],pah[2],pah[3], vl[2],vl[3]);
                mma_bf16(oacc[2*jdp+1], pal[0],pal[1],pal[2],pal[3], vh[2],vh[3]);
            }
        }
        __syncthreads();
    }

    // ---- finalize ----
    l0 += __shfl_xor_sync(0xffffffffu, l0, 1);
    l0 += __shfl_xor_sync(0xffffffffu, l0, 2);
    l1 += __shfl_xor_sync(0xffffffffu, l1, 1);
    l1 += __shfl_xor_sync(0xffffffffu, l1, 2);
    const float inv0 = 1.0f / l0;
    const float inv1 = 1.0f / l1;

#pragma unroll
    for (int jd = 0; jd < 8; ++jd) {
        const int col = h * HD + jd * 8 + 2 * t4;
        const size_t w0 = ((qrow0 + g) * E_DIM + col) >> 1;
        const size_t w1 = ((qrow0 + g + 8) * E_DIM + col) >> 1;
        uint32_t hw, lw;
        split2(oacc[jd][0] * inv0, oacc[jd][1] * inv0, hw, lw);
        reinterpret_cast<uint32_t*>(g_ah)[w0] = hw;
        reinterpret_cast<uint32_t*>(g_al)[w0] = lw;
        split2(oacc[jd][2] * inv1, oacc[jd][3] * inv1, hw, lw);
        reinterpret_cast<uint32_t*>(g_ah)[w1] = hw;
        reinterpret_cast<uint32_t*>(g_al)[w1] = lw;
    }
}

// ============================================================================
// Launch
// ============================================================================
#define GEMM_SMEM (2 * 4 * GT * 2)   // 81920 bytes
#define ATTN_SMEM (2 * 4 * AT * 2)   // 73728 bytes

extern "C" void kernel_launch(void* const* d_in, const int* in_sizes, int n_in,
                              void* d_out, int out_size)
{
    const float* x  = (const float*)d_in[0];
    const float* Wq = (const float*)d_in[1];
    const float* bq = (const float*)d_in[2];
    const float* Wk = (const float*)d_in[3];
    const float* bk = (const float*)d_in[4];
    const float* Wv = (const float*)d_in[5];
    const float* bv = (const float*)d_in[6];
    const float* Wo = (const float*)d_in[7];
    const float* bo = (const float*)d_in[8];
    float* out = (float*)d_out;

    cudaFuncSetAttribute(qkv_kernel,
        cudaFuncAttributeMaxDynamicSharedMemorySize, GEMM_SMEM);
    cudaFuncSetAttribute(outproj_kernel,
        cudaFuncAttributeMaxDynamicSharedMemorySize, GEMM_SMEM);
    cudaFuncSetAttribute(attn_kernel,
        cudaFuncAttributeMaxDynamicSharedMemorySize, ATTN_SMEM);

    // 0) split x and weights into bf16 hi/lo
    {
        const int total = NELEM + 4 * WELEM;
        split_kernel<<<total / 256, 256>>>(x, Wq, Wk, Wv, Wo);
    }
    // 1) fused QKV projections
    {
        dim3 grid(E_DIM / 128, MAX_M / 128, 3);
        qkv_kernel<<<grid, 256, GEMM_SMEM>>>(bq, bk, bv);
    }
    // 2) tensor-core flash attention
    {
        dim3 grid(S_LEN / 64, 2 * NH);
        attn_kernel<<<grid, 128, ATTN_SMEM>>>();
    }
    // 3) output projection
    {
        dim3 grid(E_DIM / 128, MAX_M / 128);
        outproj_kernel<<<grid, 256, GEMM_SMEM>>>(bo, out);
    }
}

// round 4
// speedup vs baseline: 4.7285x; 1.4625x over previous
#include <cuda_runtime.h>
#include <cuda_fp16.h>
#include <math.h>
#include <stdint.h>

// ============================================================================
// B=2, S=2048, E=1024, H=16, D=64.  M = 4096.
// All matmuls on tensor cores via fp16 2-term split:
//   a = ah + al (fp16), C = ah*bh + al*bh  (b-side lo dropped; err ~1.4e-4/stage)
// -> lo arrays only needed for A-side operands (x, q, attention-out).
// ============================================================================

#define E_DIM 1024
#define NH    16
#define HD    64
#define S_LEN 2048
#define MAX_M 4096
#define NELEM 4194304   // MAX_M * E_DIM
#define WELEM 1048576   // E_DIM * E_DIM

// ---- device scratch ----
__device__ __half g_xh[NELEM], g_xl[NELEM];
__device__ __half g_wh[4 * WELEM];            // Wq,Wk,Wv,Wo (hi only)
__device__ __half g_qh[NELEM], g_ql[NELEM];   // Q: A-side of QK^T -> hi/lo
__device__ __half g_kh[NELEM];                // K: B-side -> hi only
__device__ __half g_vh[NELEM];                // V: B-side -> hi only
__device__ __half g_ah[NELEM], g_al[NELEM];   // attn out: A-side of outproj

// ---- helpers ----
__device__ __forceinline__ void mma_f16(float c[4],
    uint32_t a0, uint32_t a1, uint32_t a2, uint32_t a3,
    uint32_t b0, uint32_t b1)
{
    asm volatile(
        "mma.sync.aligned.m16n8k16.row.col.f32.f16.f16.f32 "
        "{%0,%1,%2,%3}, {%4,%5,%6,%7}, {%8,%9}, {%0,%1,%2,%3};"
        : "+f"(c[0]), "+f"(c[1]), "+f"(c[2]), "+f"(c[3])
        : "r"(a0), "r"(a1), "r"(a2), "r"(a3), "r"(b0), "r"(b1));
}

__device__ __forceinline__ float ex2f(float x) {
    float y;
    asm("ex2.approx.ftz.f32 %0, %1;" : "=f"(y) : "f"(x));
    return y;
}

__device__ __forceinline__ void split2h(float x, float y,
                                        uint32_t& hw, uint32_t& lw)
{
    __half hx = __float2half_rn(x);
    __half hy = __float2half_rn(y);
    __half lx = __float2half_rn(x - __half2float(hx));
    __half ly = __float2half_rn(y - __half2float(hy));
    __half2 H = __halves2half2(hx, hy);
    __half2 L = __halves2half2(lx, ly);
    hw = *reinterpret_cast<uint32_t*>(&H);
    lw = *reinterpret_cast<uint32_t*>(&L);
}

__device__ __forceinline__ uint32_t pack2h(float x, float y) {
    __half2 t = __halves2half2(__float2half_rn(x), __float2half_rn(y));
    return *reinterpret_cast<uint32_t*>(&t);
}

__device__ __forceinline__ uint32_t smem_u32(const void* p) {
    return (uint32_t)__cvta_generic_to_shared(p);
}

__device__ __forceinline__ void ldsm4(uint32_t& r0, uint32_t& r1,
                                      uint32_t& r2, uint32_t& r3, uint32_t a) {
    asm volatile("ldmatrix.sync.aligned.m8n8.x4.shared.b16 {%0,%1,%2,%3}, [%4];"
        : "=r"(r0), "=r"(r1), "=r"(r2), "=r"(r3) : "r"(a));
}

__device__ __forceinline__ void ldsm4t(uint32_t& r0, uint32_t& r1,
                                       uint32_t& r2, uint32_t& r3, uint32_t a) {
    asm volatile("ldmatrix.sync.aligned.m8n8.x4.trans.shared.b16 {%0,%1,%2,%3}, [%4];"
        : "=r"(r0), "=r"(r1), "=r"(r2), "=r"(r3) : "r"(a));
}

__device__ __forceinline__ void cp16(uint32_t dst, const void* src) {
    asm volatile("cp.async.cg.shared.global [%0], [%1], 16;"
        :: "r"(dst), "l"(src));
}
#define CP_COMMIT() asm volatile("cp.async.commit_group;")
#define CP_WAIT1()  asm volatile("cp.async.wait_group 1;")
#define CP_WAIT0()  asm volatile("cp.async.wait_group 0;")

// ============================================================================
// Pre-split: x -> hi/lo, weights -> hi only
// ============================================================================
__global__ __launch_bounds__(256) void split_kernel(
    const float* __restrict__ x,
    const float* __restrict__ Wq, const float* __restrict__ Wk,
    const float* __restrict__ Wv, const float* __restrict__ Wo)
{
    int i = blockIdx.x * 256 + threadIdx.x;
    if (i < NELEM) {
        float v = x[i];
        __half hi = __float2half_rn(v);
        g_xh[i] = hi;
        g_xl[i] = __float2half_rn(v - __half2float(hi));
    } else {
        int j = i - NELEM;
        int w = j >> 20;
        int off = j & (WELEM - 1);
        const float* W = (w == 0) ? Wq : (w == 1) ? Wk : (w == 2) ? Wv : Wo;
        g_wh[j] = __float2half_rn(W[off]);
    }
}

// ============================================================================
// Split-fp16 GEMM:  C[m,n] = sum_k A[m,k]*W[n,k] + bias[n]
// BM=128, BN=128, BK=32, 256 thr (4m x 2n warps, warp tile 32x64).
// cp.async double buffer (3 arrays: Ah, Al, Wh); ldmatrix.x4 fragments.
// OutMode: 0 = fp32 out, 1 = fp16 hi only, 2 = fp16 hi+lo.
// ============================================================================
#define GROW 40
#define GT   (128 * GROW)

template<int OutMode>
__device__ __forceinline__ void gemm_core(
    const __half* __restrict__ Ah, const __half* __restrict__ Al,
    const __half* __restrict__ Wh,
    const float* __restrict__ bias,
    float* __restrict__ outF,
    __half* __restrict__ Oh, __half* __restrict__ Ol)
{
    extern __shared__ __half sm[];
    const int tid  = threadIdx.x;
    const int lane = tid & 31;
    const int wid  = tid >> 5;
    const int wm   = wid & 3;
    const int wn   = wid >> 2;
    const int g    = lane >> 2;
    const int t4   = lane & 3;
    const int bm   = blockIdx.y * 128;
    const int bn   = blockIdx.x * 128;

    float acc[2][8][4];
#pragma unroll
    for (int s = 0; s < 2; ++s)
#pragma unroll
        for (int j = 0; j < 8; ++j)
#pragma unroll
            for (int e = 0; e < 4; ++e) acc[s][j][e] = 0.0f;

    auto load_stage = [&](int s, int kt) {
#pragma unroll
        for (int i = 0; i < 6; ++i) {
            const int a   = i >> 1;                 // 0:Ah 1:Al 2:Wh
            const int c   = (i & 1) * 256 + tid;    // [0,512)
            const int row = c >> 2;
            const int col = (c & 3) * 8;
            const __half* base = (a == 0) ? Ah : (a == 1) ? Al : Wh;
            const int rb = (a < 2) ? bm : bn;
            cp16(smem_u32(sm + (s * 3 + a) * GT + row * GROW + col),
                 base + (size_t)(rb + row) * E_DIM + kt + col);
        }
    };

    load_stage(0, 0);
    CP_COMMIT();

    const int NT = E_DIM / 32;
    for (int t = 0; t < NT; ++t) {
        const int s = t & 1;
        if (t + 1 < NT) {
            load_stage(s ^ 1, (t + 1) * 32);
            CP_COMMIT();
            CP_WAIT1();
        } else {
            CP_WAIT0();
        }
        __syncthreads();

        const uint32_t bAh = smem_u32(sm + (s * 3 + 0) * GT);
        const uint32_t bAl = smem_u32(sm + (s * 3 + 1) * GT);
        const uint32_t bWh = smem_u32(sm + (s * 3 + 2) * GT);

#pragma unroll
        for (int kk = 0; kk < 2; ++kk) {
            uint32_t ah[2][4], al[2][4];
            const int ka = kk * 16 + (lane >> 4) * 8;
#pragma unroll
            for (int ss = 0; ss < 2; ++ss) {
                const int m = wm * 32 + ss * 16 + (lane & 15);
                const uint32_t off = (uint32_t)(m * GROW + ka) * 2;
                ldsm4(ah[ss][0], ah[ss][1], ah[ss][2], ah[ss][3], bAh + off);
                ldsm4(al[ss][0], al[ss][1], al[ss][2], al[ss][3], bAl + off);
            }
            const int kb  = kk * 16 + ((lane >> 3) & 1) * 8;
            const int nb0 = (lane & 7) + ((lane >> 4) << 3);
#pragma unroll
            for (int jp = 0; jp < 4; ++jp) {
                const int n = wn * 64 + jp * 16 + nb0;
                const uint32_t off = (uint32_t)(n * GROW + kb) * 2;
                uint32_t bh[4];
                ldsm4(bh[0], bh[1], bh[2], bh[3], bWh + off);
#pragma unroll
                for (int ss = 0; ss < 2; ++ss) {
                    mma_f16(acc[ss][2*jp],   ah[ss][0],ah[ss][1],ah[ss][2],ah[ss][3], bh[0],bh[1]);
                    mma_f16(acc[ss][2*jp],   al[ss][0],al[ss][1],al[ss][2],al[ss][3], bh[0],bh[1]);
                    mma_f16(acc[ss][2*jp+1], ah[ss][0],ah[ss][1],ah[ss][2],ah[ss][3], bh[2],bh[3]);
                    mma_f16(acc[ss][2*jp+1], al[ss][0],al[ss][1],al[ss][2],al[ss][3], bh[2],bh[3]);
                }
            }
        }
        __syncthreads();
    }

    // epilogue
#pragma unroll
    for (int j = 0; j < 8; ++j) {
        const int col = bn + wn * 64 + j * 8 + 2 * t4;
        const float b0 = bias[col], b1 = bias[col + 1];
#pragma unroll
        for (int ss = 0; ss < 2; ++ss) {
            const int r0 = bm + wm * 32 + ss * 16 + g;
            const float v0 = acc[ss][j][0] + b0, v1 = acc[ss][j][1] + b1;
            const float v2 = acc[ss][j][2] + b0, v3 = acc[ss][j][3] + b1;
            const size_t w0 = ((size_t)r0 * E_DIM + col) >> 1;
            const size_t w1 = ((size_t)(r0 + 8) * E_DIM + col) >> 1;
            if (OutMode == 2) {
                uint32_t hw, lw;
                split2h(v0, v1, hw, lw);
                reinterpret_cast<uint32_t*>(Oh)[w0] = hw;
                reinterpret_cast<uint32_t*>(Ol)[w0] = lw;
                split2h(v2, v3, hw, lw);
                reinterpret_cast<uint32_t*>(Oh)[w1] = hw;
                reinterpret_cast<uint32_t*>(Ol)[w1] = lw;
            } else if (OutMode == 1) {
                reinterpret_cast<uint32_t*>(Oh)[w0] = pack2h(v0, v1);
                reinterpret_cast<uint32_t*>(Oh)[w1] = pack2h(v2, v3);
            } else {
                float2 p0; p0.x = v0; p0.y = v1;
                float2 p1; p1.x = v2; p1.y = v3;
                *reinterpret_cast<float2*>(outF + (size_t)r0 * E_DIM + col) = p0;
                *reinterpret_cast<float2*>(outF + (size_t)(r0 + 8) * E_DIM + col) = p1;
            }
        }
    }
}

__global__ __launch_bounds__(256, 2) void qkv_kernel(
    const float* __restrict__ bq, const float* __restrict__ bk,
    const float* __restrict__ bv)
{
    const int z = blockIdx.z;
    const __half* Wh = g_wh + (size_t)z * WELEM;
    if (z == 0) {
        gemm_core<2>(g_xh, g_xl, Wh, bq, nullptr, g_qh, g_ql);
    } else if (z == 1) {
        gemm_core<1>(g_xh, g_xl, Wh, bk, nullptr, g_kh, nullptr);
    } else {
        gemm_core<1>(g_xh, g_xl, Wh, bv, nullptr, g_vh, nullptr);
    }
}

__global__ __launch_bounds__(256, 2) void outproj_kernel(
    const float* __restrict__ bo, float* __restrict__ out)
{
    gemm_core<0>(g_ah, g_al, g_wh + (size_t)3 * WELEM, bo, out, nullptr, nullptr);
}

// ============================================================================
// Tensor-core flash attention (128 thr, 4 warps, Q tile 64, K tiles of 64).
// cp.async double-buffered Kh/Vh (hi only); ldmatrix K, ldmatrix.trans V.
// QK^T: qh*kh + ql*kh.  PV: ph*vh + pl*vh.
// ============================================================================
#define APAD 72
#define AT   (64 * APAD)

__global__ __launch_bounds__(128) void attn_kernel()
{
    extern __shared__ __half sm[];
    const int tid  = threadIdx.x;
    const int lane = tid & 31;
    const int wid  = tid >> 5;
    const int g    = lane >> 2;
    const int t4   = lane & 3;

    const int bh = blockIdx.y;
    const int b  = bh >> 4;
    const int h  = bh & 15;
    const int q0 = blockIdx.x * 64 + wid * 16;
    const size_t qrow0 = (size_t)(b * S_LEN + q0);

    const float cs = 0.18033688011112042f;   // (1/8) * log2(e)

    uint32_t qfh[4][4], qfl[4][4];
#pragma unroll
    for (int kk = 0; kk < 4; ++kk) {
        const size_t i0 = (qrow0 + g) * E_DIM + h * HD + kk * 16 + 2 * t4;
        const size_t i1 = (qrow0 + g + 8) * E_DIM + h * HD + kk * 16 + 2 * t4;
        qfh[kk][0] = *reinterpret_cast<const uint32_t*>(g_qh + i0);
        qfh[kk][1] = *reinterpret_cast<const uint32_t*>(g_qh + i1);
        qfh[kk][2] = *reinterpret_cast<const uint32_t*>(g_qh + i0 + 8);
        qfh[kk][3] = *reinterpret_cast<const uint32_t*>(g_qh + i1 + 8);
        qfl[kk][0] = *reinterpret_cast<const uint32_t*>(g_ql + i0);
        qfl[kk][1] = *reinterpret_cast<const uint32_t*>(g_ql + i1);
        qfl[kk][2] = *reinterpret_cast<const uint32_t*>(g_ql + i0 + 8);
        qfl[kk][3] = *reinterpret_cast<const uint32_t*>(g_ql + i1 + 8);
    }

    float oacc[8][4];
#pragma unroll
    for (int jd = 0; jd < 8; ++jd)
#pragma unroll
        for (int e = 0; e < 4; ++e) oacc[jd][e] = 0.0f;
    float m0 = -INFINITY, m1 = -INFINITY, l0 = 0.0f, l1 = 0.0f;

    auto load_stage = [&](int s, int kt) {
#pragma unroll
        for (int i = 0; i < 8; ++i) {
            const int a   = i >> 2;                 // 0:Kh 1:Vh
            const int c   = (i & 3) * 128 + tid;    // [0,512)
            const int row = c >> 3;
            const int col = (c & 7) * 8;
            const __half* base = (a == 0) ? g_kh : g_vh;
            cp16(smem_u32(sm + (s * 2 + a) * AT + row * APAD + col),
                 base + (size_t)(b * S_LEN + kt * 64 + row) * E_DIM + h * HD + col);
        }
    };

    load_stage(0, 0);
    CP_COMMIT();

    const int NT = S_LEN / 64;
    for (int t = 0; t < NT; ++t) {
        const int s = t & 1;
        if (t + 1 < NT) {
            load_stage(s ^ 1, t + 1);
            CP_COMMIT();
            CP_WAIT1();
        } else {
            CP_WAIT0();
        }
        __syncthreads();

        const uint32_t bKh = smem_u32(sm + (s * 2 + 0) * AT);
        const uint32_t bVh = smem_u32(sm + (s * 2 + 1) * AT);

        // ---- QK^T ----
        float sacc[8][4];
#pragma unroll
        for (int j = 0; j < 8; ++j)
#pragma unroll
            for (int e = 0; e < 4; ++e) sacc[j][e] = 0.0f;

        const int nb0 = (lane & 7) + ((lane >> 4) << 3);
        const int kb0 = ((lane >> 3) & 1) * 8;
#pragma unroll
        for (int jp = 0; jp < 4; ++jp) {
            const int n = jp * 16 + nb0;
#pragma unroll
            for (int kk = 0; kk < 4; ++kk) {
                const uint32_t off = (uint32_t)(n * APAD + kk * 16 + kb0) * 2;
                uint32_t kh[4];
                ldsm4(kh[0], kh[1], kh[2], kh[3], bKh + off);
                mma_f16(sacc[2*jp],   qfh[kk][0],qfh[kk][1],qfh[kk][2],qfh[kk][3], kh[0],kh[1]);
                mma_f16(sacc[2*jp],   qfl[kk][0],qfl[kk][1],qfl[kk][2],qfl[kk][3], kh[0],kh[1]);
                mma_f16(sacc[2*jp+1], qfh[kk][0],qfh[kk][1],qfh[kk][2],qfh[kk][3], kh[2],kh[3]);
                mma_f16(sacc[2*jp+1], qfl[kk][0],qfl[kk][1],qfl[kk][2],qfl[kk][3], kh[2],kh[3]);
            }
        }

        // ---- online softmax ----
        float nm0 = m0, nm1 = m1;
#pragma unroll
        for (int j = 0; j < 8; ++j) {
            nm0 = fmaxf(nm0, fmaxf(sacc[j][0], sacc[j][1]));
            nm1 = fmaxf(nm1, fmaxf(sacc[j][2], sacc[j][3]));
        }
        nm0 = fmaxf(nm0, __shfl_xor_sync(0xffffffffu, nm0, 1));
        nm0 = fmaxf(nm0, __shfl_xor_sync(0xffffffffu, nm0, 2));
        nm1 = fmaxf(nm1, __shfl_xor_sync(0xffffffffu, nm1, 1));
        nm1 = fmaxf(nm1, __shfl_xor_sync(0xffffffffu, nm1, 2));

        const float c0 = ex2f((m0 - nm0) * cs);
        const float c1 = ex2f((m1 - nm1) * cs);
        m0 = nm0; m1 = nm1;
        l0 *= c0;  l1 *= c1;

#pragma unroll
        for (int j = 0; j < 8; ++j) {
            const float p0 = ex2f((sacc[j][0] - m0) * cs);
            const float p1 = ex2f((sacc[j][1] - m0) * cs);
            const float p2 = ex2f((sacc[j][2] - m1) * cs);
            const float p3 = ex2f((sacc[j][3] - m1) * cs);
            l0 += p0 + p1;
            l1 += p2 + p3;
            sacc[j][0] = p0; sacc[j][1] = p1; sacc[j][2] = p2; sacc[j][3] = p3;
        }
#pragma unroll
        for (int jd = 0; jd < 8; ++jd) {
            oacc[jd][0] *= c0; oacc[jd][1] *= c0;
            oacc[jd][2] *= c1; oacc[jd][3] *= c1;
        }

        // ---- PV ----
        const int krb = ((lane >> 3) & 1) * 8 + (lane & 7);
        const int dcb = (lane >> 4) * 8;
#pragma unroll
        for (int kk = 0; kk < 4; ++kk) {
            uint32_t pah[4], pal[4];
            split2h(sacc[2*kk][0],   sacc[2*kk][1],   pah[0], pal[0]);
            split2h(sacc[2*kk][2],   sacc[2*kk][3],   pah[1], pal[1]);
            split2h(sacc[2*kk+1][0], sacc[2*kk+1][1], pah[2], pal[2]);
            split2h(sacc[2*kk+1][2], sacc[2*kk+1][3], pah[3], pal[3]);
            const int kr = kk * 16 + krb;
#pragma unroll
            for (int jdp = 0; jdp < 4; ++jdp) {
                const int dc = jdp * 16 + dcb;
                const uint32_t off = (uint32_t)(kr * APAD + dc) * 2;
                uint32_t vh[4];
                ldsm4t(vh[0], vh[1], vh[2], vh[3], bVh + off);
                mma_f16(oacc[2*jdp],   pah[0],pah[1],pah[2],pah[3], vh[0],vh[1]);
                mma_f16(oacc[2*jdp],   pal[0],pal[1],pal[2],pal[3], vh[0],vh[1]);
                mma_f16(oacc[2*jdp+1], pah[0],pah[1],pah[2],pah[3], vh[2],vh[3]);
                mma_f16(oacc[2*jdp+1], pal[0],pal[1],pal[2],pal[3], vh[2],vh[3]);
            }
        }
        __syncthreads();
    }

    // ---- finalize ----
    l0 += __shfl_xor_sync(0xffffffffu, l0, 1);
    l0 += __shfl_xor_sync(0xffffffffu, l0, 2);
    l1 += __shfl_xor_sync(0xffffffffu, l1, 1);
    l1 += __shfl_xor_sync(0xffffffffu, l1, 2);
    const float inv0 = 1.0f / l0;
    const float inv1 = 1.0f / l1;

#pragma unroll
    for (int jd = 0; jd < 8; ++jd) {
        const int col = h * HD + jd * 8 + 2 * t4;
        const size_t w0 = ((qrow0 + g) * E_DIM + col) >> 1;
        const size_t w1 = ((qrow0 + g + 8) * E_DIM + col) >> 1;
        uint32_t hw, lw;
        split2h(oacc[jd][0] * inv0, oacc[jd][1] * inv0, hw, lw);
        reinterpret_cast<uint32_t*>(g_ah)[w0] = hw;
        reinterpret_cast<uint32_t*>(g_al)[w0] = lw;
        split2h(oacc[jd][2] * inv1, oacc[jd][3] * inv1, hw, lw);
        reinterpret_cast<uint32_t*>(g_ah)[w1] = hw;
        reinterpret_cast<uint32_t*>(g_al)[w1] = lw;
    }
}

// ============================================================================
// Launch
// ============================================================================
#define GEMM_SMEM (2 * 3 * GT * 2)   // 61440 bytes
#define ATTN_SMEM (2 * 2 * AT * 2)   // 36864 bytes

extern "C" void kernel_launch(void* const* d_in, const int* in_sizes, int n_in,
                              void* d_out, int out_size)
{
    const float* x  = (const float*)d_in[0];
    const float* bq = (const float*)d_in[2];
    const float* bk = (const float*)d_in[4];
    const float* bv = (const float*)d_in[6];
    const float* bo = (const float*)d_in[8];
    float* out = (float*)d_out;

    cudaFuncSetAttribute(qkv_kernel,
        cudaFuncAttributeMaxDynamicSharedMemorySize, GEMM_SMEM);
    cudaFuncSetAttribute(outproj_kernel,
        cudaFuncAttributeMaxDynamicSharedMemorySize, GEMM_SMEM);
    cudaFuncSetAttribute(attn_kernel,
        cudaFuncAttributeMaxDynamicSharedMemorySize, ATTN_SMEM);

    // 0) split x (hi/lo) and weights (hi)
    {
        const int total = NELEM + 4 * WELEM;
        split_kernel<<<total / 256, 256>>>(x,
            (const float*)d_in[1], (const float*)d_in[3],
            (const float*)d_in[5], (const float*)d_in[7]);
    }
    // 1) fused QKV projections
    {
        dim3 grid(E_DIM / 128, MAX_M / 128, 3);
        qkv_kernel<<<grid, 256, GEMM_SMEM>>>(bq, bk, bv);
    }
    // 2) tensor-core flash attention
    {
        dim3 grid(S_LEN / 64, 2 * NH);
        attn_kernel<<<grid, 128, ATTN_SMEM>>>();
    }
    // 3) output projection
    {
        dim3 grid(E_DIM / 128, MAX_M / 128);
        outproj_kernel<<<grid, 256, GEMM_SMEM>>>(bo, out);
    }
}

// round 8
// speedup vs baseline: 5.1305x; 1.0850x over previous
#include <cuda_runtime.h>
#include <cuda_fp16.h>
#include <math.h>
#include <stdint.h>

// ============================================================================
// B=2, S=2048, E=1024, H=16, D=64.  M = 4096.
// All matmuls on mma.sync (HMMA) — tcgen05 is NOT compilable in this harness
// (ptxas target is sm_100, which lacks the arch-variant tcgen05 features).
// fp16 2-term split: a = ah + al, C = ah*bh + al*bh (b-side lo dropped).
// PV additionally drops P-lo (P is softmax-bounded in [0,1]).
// ============================================================================

#define E_DIM 1024
#define NH    16
#define HD    64
#define S_LEN 2048
#define MAX_M 4096
#define NELEM 4194304
#define WELEM 1048576

__device__ __half g_xh[NELEM], g_xl[NELEM];
__device__ __half g_wh[4 * WELEM];
__device__ __half g_qh[NELEM], g_ql[NELEM];
__device__ __half g_kh[NELEM];
__device__ __half g_vh[NELEM];
__device__ __half g_ah[NELEM], g_al[NELEM];

// ---- helpers ----
__device__ __forceinline__ void mma_f16(float c[4],
    uint32_t a0, uint32_t a1, uint32_t a2, uint32_t a3,
    uint32_t b0, uint32_t b1)
{
    asm volatile(
        "mma.sync.aligned.m16n8k16.row.col.f32.f16.f16.f32 "
        "{%0,%1,%2,%3}, {%4,%5,%6,%7}, {%8,%9}, {%0,%1,%2,%3};"
        : "+f"(c[0]), "+f"(c[1]), "+f"(c[2]), "+f"(c[3])
        : "r"(a0), "r"(a1), "r"(a2), "r"(a3), "r"(b0), "r"(b1));
}

__device__ __forceinline__ float ex2f(float x) {
    float y;
    asm("ex2.approx.ftz.f32 %0, %1;" : "=f"(y) : "f"(x));
    return y;
}

__device__ __forceinline__ void split2h(float x, float y,
                                        uint32_t& hw, uint32_t& lw)
{
    __half hx = __float2half_rn(x);
    __half hy = __float2half_rn(y);
    __half lx = __float2half_rn(x - __half2float(hx));
    __half ly = __float2half_rn(y - __half2float(hy));
    __half2 H = __halves2half2(hx, hy);
    __half2 L = __halves2half2(lx, ly);
    hw = *reinterpret_cast<uint32_t*>(&H);
    lw = *reinterpret_cast<uint32_t*>(&L);
}

__device__ __forceinline__ uint32_t pack2h(float x, float y) {
    __half2 t = __halves2half2(__float2half_rn(x), __float2half_rn(y));
    return *reinterpret_cast<uint32_t*>(&t);
}

__device__ __forceinline__ uint32_t smem_u32(const void* p) {
    return (uint32_t)__cvta_generic_to_shared(p);
}

__device__ __forceinline__ void ldsm4(uint32_t& r0, uint32_t& r1,
                                      uint32_t& r2, uint32_t& r3, uint32_t a) {
    asm volatile("ldmatrix.sync.aligned.m8n8.x4.shared.b16 {%0,%1,%2,%3}, [%4];"
        : "=r"(r0), "=r"(r1), "=r"(r2), "=r"(r3) : "r"(a));
}

__device__ __forceinline__ void ldsm4t(uint32_t& r0, uint32_t& r1,
                                       uint32_t& r2, uint32_t& r3, uint32_t a) {
    asm volatile("ldmatrix.sync.aligned.m8n8.x4.trans.shared.b16 {%0,%1,%2,%3}, [%4];"
        : "=r"(r0), "=r"(r1), "=r"(r2), "=r"(r3) : "r"(a));
}

__device__ __forceinline__ void cp16(uint32_t dst, const void* src) {
    asm volatile("cp.async.cg.shared.global [%0], [%1], 16;"
        :: "r"(dst), "l"(src));
}
#define CP_COMMIT() asm volatile("cp.async.commit_group;")
#define CP_WAIT1()  asm volatile("cp.async.wait_group 1;")
#define CP_WAIT0()  asm volatile("cp.async.wait_group 0;")

// ============================================================================
// Pre-split: x -> hi/lo, weights -> hi only
// ============================================================================
__global__ __launch_bounds__(256) void split_kernel(
    const float* __restrict__ x,
    const float* __restrict__ Wq, const float* __restrict__ Wk,
    const float* __restrict__ Wv, const float* __restrict__ Wo)
{
    int i = blockIdx.x * 256 + threadIdx.x;
    if (i < NELEM) {
        float v = x[i];
        __half hi = __float2half_rn(v);
        g_xh[i] = hi;
        g_xl[i] = __float2half_rn(v - __half2float(hi));
    } else {
        int j = i - NELEM;
        int w = j >> 20;
        int off = j & (WELEM - 1);
        const float* W = (w == 0) ? Wq : (w == 1) ? Wk : (w == 2) ? Wv : Wo;
        g_wh[j] = __float2half_rn(W[off]);
    }
}

// ============================================================================
// Split-fp16 GEMM (round-4 passing version, unchanged)
// BM=128, BN=128, BK=32, 256 thr; cp.async double buffer; ldmatrix.x4.
// ============================================================================
#define GROW 40
#define GT   (128 * GROW)

template<int OutMode>
__device__ __forceinline__ void gemm_core(
    const __half* __restrict__ Ah, const __half* __restrict__ Al,
    const __half* __restrict__ Wh,
    const float* __restrict__ bias,
    float* __restrict__ outF,
    __half* __restrict__ Oh, __half* __restrict__ Ol)
{
    extern __shared__ __half sm[];
    const int tid  = threadIdx.x;
    const int lane = tid & 31;
    const int wid  = tid >> 5;
    const int wm   = wid & 3;
    const int wn   = wid >> 2;
    const int g    = lane >> 2;
    const int t4   = lane & 3;
    const int bm   = blockIdx.y * 128;
    const int bn   = blockIdx.x * 128;

    float acc[2][8][4];
#pragma unroll
    for (int s = 0; s < 2; ++s)
#pragma unroll
        for (int j = 0; j < 8; ++j)
#pragma unroll
            for (int e = 0; e < 4; ++e) acc[s][j][e] = 0.0f;

    auto load_stage = [&](int s, int kt) {
#pragma unroll
        for (int i = 0; i < 6; ++i) {
            const int a   = i >> 1;
            const int c   = (i & 1) * 256 + tid;
            const int row = c >> 2;
            const int col = (c & 3) * 8;
            const __half* base = (a == 0) ? Ah : (a == 1) ? Al : Wh;
            const int rb = (a < 2) ? bm : bn;
            cp16(smem_u32(sm + (s * 3 + a) * GT + row * GROW + col),
                 base + (size_t)(rb + row) * E_DIM + kt + col);
        }
    };

    load_stage(0, 0);
    CP_COMMIT();

    const int NT = E_DIM / 32;
    for (int t = 0; t < NT; ++t) {
        const int s = t & 1;
        if (t + 1 < NT) {
            load_stage(s ^ 1, (t + 1) * 32);
            CP_COMMIT();
            CP_WAIT1();
        } else {
            CP_WAIT0();
        }
        __syncthreads();

        const uint32_t bAh = smem_u32(sm + (s * 3 + 0) * GT);
        const uint32_t bAl = smem_u32(sm + (s * 3 + 1) * GT);
        const uint32_t bWh = smem_u32(sm + (s * 3 + 2) * GT);

#pragma unroll
        for (int kk = 0; kk < 2; ++kk) {
            uint32_t ah[2][4], al[2][4];
            const int ka = kk * 16 + (lane >> 4) * 8;
#pragma unroll
            for (int ss = 0; ss < 2; ++ss) {
                const int m = wm * 32 + ss * 16 + (lane & 15);
                const uint32_t off = (uint32_t)(m * GROW + ka) * 2;
                ldsm4(ah[ss][0], ah[ss][1], ah[ss][2], ah[ss][3], bAh + off);
                ldsm4(al[ss][0], al[ss][1], al[ss][2], al[ss][3], bAl + off);
            }
            const int kb  = kk * 16 + ((lane >> 3) & 1) * 8;
            const int nb0 = (lane & 7) + ((lane >> 4) << 3);
#pragma unroll
            for (int jp = 0; jp < 4; ++jp) {
                const int n = wn * 64 + jp * 16 + nb0;
                const uint32_t off = (uint32_t)(n * GROW + kb) * 2;
                uint32_t bh[4];
                ldsm4(bh[0], bh[1], bh[2], bh[3], bWh + off);
#pragma unroll
                for (int ss = 0; ss < 2; ++ss) {
                    mma_f16(acc[ss][2*jp],   ah[ss][0],ah[ss][1],ah[ss][2],ah[ss][3], bh[0],bh[1]);
                    mma_f16(acc[ss][2*jp],   al[ss][0],al[ss][1],al[ss][2],al[ss][3], bh[0],bh[1]);
                    mma_f16(acc[ss][2*jp+1], ah[ss][0],ah[ss][1],ah[ss][2],ah[ss][3], bh[2],bh[3]);
                    mma_f16(acc[ss][2*jp+1], al[ss][0],al[ss][1],al[ss][2],al[ss][3], bh[2],bh[3]);
                }
            }
        }
        __syncthreads();
    }

    // epilogue
#pragma unroll
    for (int j = 0; j < 8; ++j) {
        const int col = bn + wn * 64 + j * 8 + 2 * t4;
        const float b0 = bias[col], b1 = bias[col + 1];
#pragma unroll
        for (int ss = 0; ss < 2; ++ss) {
            const int r0 = bm + wm * 32 + ss * 16 + g;
            const float v0 = acc[ss][j][0] + b0, v1 = acc[ss][j][1] + b1;
            const float v2 = acc[ss][j][2] + b0, v3 = acc[ss][j][3] + b1;
            const size_t w0 = ((size_t)r0 * E_DIM + col) >> 1;
            const size_t w1 = ((size_t)(r0 + 8) * E_DIM + col) >> 1;
            if (OutMode == 2) {
                uint32_t hw, lw;
                split2h(v0, v1, hw, lw);
                reinterpret_cast<uint32_t*>(Oh)[w0] = hw;
                reinterpret_cast<uint32_t*>(Ol)[w0] = lw;
                split2h(v2, v3, hw, lw);
                reinterpret_cast<uint32_t*>(Oh)[w1] = hw;
                reinterpret_cast<uint32_t*>(Ol)[w1] = lw;
            } else if (OutMode == 1) {
                reinterpret_cast<uint32_t*>(Oh)[w0] = pack2h(v0, v1);
                reinterpret_cast<uint32_t*>(Oh)[w1] = pack2h(v2, v3);
            } else {
                float2 p0; p0.x = v0; p0.y = v1;
                float2 p1; p1.x = v2; p1.y = v3;
                *reinterpret_cast<float2*>(outF + (size_t)r0 * E_DIM + col) = p0;
                *reinterpret_cast<float2*>(outF + (size_t)(r0 + 8) * E_DIM + col) = p1;
            }
        }
    }
}

__global__ __launch_bounds__(256, 2) void qkv_kernel(
    const float* __restrict__ bq, const float* __restrict__ bk,
    const float* __restrict__ bv)
{
    const int z = blockIdx.z;
    const __half* Wh = g_wh + (size_t)z * WELEM;
    if (z == 0)
        gemm_core<2>(g_xh, g_xl, Wh, bq, nullptr, g_qh, g_ql);
    else if (z == 1)
        gemm_core<1>(g_xh, g_xl, Wh, bk, nullptr, g_kh, nullptr);
    else
        gemm_core<1>(g_xh, g_xl, Wh, bv, nullptr, g_vh, nullptr);
}

__global__ __launch_bounds__(256, 2) void outproj_kernel(
    const float* __restrict__ bo, float* __restrict__ out)
{
    gemm_core<0>(g_ah, g_al, g_wh + (size_t)3 * WELEM, bo, out, nullptr, nullptr);
}

// ============================================================================
// Flash attention: 256 thr (8 warps), Q tile 128 (16 rows/warp), K tiles of 64.
// K/V gmem traffic per block HALVED vs the 64-query version.
// QK^T: 2-term (q hi+lo).  PV: 1-term (P fp16, lo dropped).
// ============================================================================
#define APAD 72
#define AT   (64 * APAD)
#define ATTN_SMEM (2 * 2 * AT * 2)   // 36864 B

__global__ __launch_bounds__(256) void attn_kernel()
{
    extern __shared__ __half sm[];
    const int tid  = threadIdx.x;
    const int lane = tid & 31;
    const int wid  = tid >> 5;          // 0..7
    const int g    = lane >> 2;
    const int t4   = lane & 3;

    const int bh = blockIdx.y;
    const int b  = bh >> 4;
    const int h  = bh & 15;
    const int q0 = blockIdx.x * 128 + wid * 16;
    const size_t qrow0 = (size_t)(b * S_LEN + q0);

    const float cs = 0.18033688011112042f;   // (1/8) * log2(e)

    uint32_t qfh[4][4], qfl[4][4];
#pragma unroll
    for (int kk = 0; kk < 4; ++kk) {
        const size_t i0 = (qrow0 + g) * E_DIM + h * HD + kk * 16 + 2 * t4;
        const size_t i1 = (qrow0 + g + 8) * E_DIM + h * HD + kk * 16 + 2 * t4;
        qfh[kk][0] = *reinterpret_cast<const uint32_t*>(g_qh + i0);
        qfh[kk][1] = *reinterpret_cast<const uint32_t*>(g_qh + i1);
        qfh[kk][2] = *reinterpret_cast<const uint32_t*>(g_qh + i0 + 8);
        qfh[kk][3] = *reinterpret_cast<const uint32_t*>(g_qh + i1 + 8);
        qfl[kk][0] = *reinterpret_cast<const uint32_t*>(g_ql + i0);
        qfl[kk][1] = *reinterpret_cast<const uint32_t*>(g_ql + i1);
        qfl[kk][2] = *reinterpret_cast<const uint32_t*>(g_ql + i0 + 8);
        qfl[kk][3] = *reinterpret_cast<const uint32_t*>(g_ql + i1 + 8);
    }

    float oacc[8][4];
#pragma unroll
    for (int jd = 0; jd < 8; ++jd)
#pragma unroll
        for (int e = 0; e < 4; ++e) oacc[jd][e] = 0.0f;
    float m0 = -INFINITY, m1 = -INFINITY, l0 = 0.0f, l1 = 0.0f;

    // stage K/V hi tiles: each 64 rows x 64 halves (128B/row); 1024 cp16 total
    auto load_stage = [&](int s, int kt) {
#pragma unroll
        for (int i = 0; i < 4; ++i) {
            const int idx = i * 256 + tid;       // [0, 1024)
            const int a   = idx >> 9;            // 0:Kh 1:Vh
            const int rem = idx & 511;
            const int row = rem >> 3;            // 0..63
            const int col = (rem & 7) * 8;
            const __half* base = (a == 0) ? g_kh : g_vh;
            cp16(smem_u32(sm + (s * 2 + a) * AT + row * APAD + col),
                 base + (size_t)(b * S_LEN + kt * 64 + row) * E_DIM + h * HD + col);
        }
    };

    load_stage(0, 0);
    CP_COMMIT();

    const int NT = S_LEN / 64;
    for (int t = 0; t < NT; ++t) {
        const int s = t & 1;
        if (t + 1 < NT) {
            load_stage(s ^ 1, t + 1);
            CP_COMMIT();
            CP_WAIT1();
        } else {
            CP_WAIT0();
        }
        __syncthreads();

        const uint32_t bKh = smem_u32(sm + (s * 2 + 0) * AT);
        const uint32_t bVh = smem_u32(sm + (s * 2 + 1) * AT);

        // ---- QK^T ----
        float sacc[8][4];
#pragma unroll
        for (int j = 0; j < 8; ++j)
#pragma unroll
            for (int e = 0; e < 4; ++e) sacc[j][e] = 0.0f;

        const int nb0 = (lane & 7) + ((lane >> 4) << 3);
        const int kb0 = ((lane >> 3) & 1) * 8;
#pragma unroll
        for (int jp = 0; jp < 4; ++jp) {
            const int n = jp * 16 + nb0;
#pragma unroll
            for (int kk = 0; kk < 4; ++kk) {
                const uint32_t off = (uint32_t)(n * APAD + kk * 16 + kb0) * 2;
                uint32_t kh[4];
                ldsm4(kh[0], kh[1], kh[2], kh[3], bKh + off);
                mma_f16(sacc[2*jp],   qfh[kk][0],qfh[kk][1],qfh[kk][2],qfh[kk][3], kh[0],kh[1]);
                mma_f16(sacc[2*jp],   qfl[kk][0],qfl[kk][1],qfl[kk][2],qfl[kk][3], kh[0],kh[1]);
                mma_f16(sacc[2*jp+1], qfh[kk][0],qfh[kk][1],qfh[kk][2],qfh[kk][3], kh[2],kh[3]);
                mma_f16(sacc[2*jp+1], qfl[kk][0],qfl[kk][1],qfl[kk][2],qfl[kk][3], kh[2],kh[3]);
            }
        }

        // ---- online softmax ----
        float nm0 = m0, nm1 = m1;
#pragma unroll
        for (int j = 0; j < 8; ++j) {
            nm0 = fmaxf(nm0, fmaxf(sacc[j][0], sacc[j][1]));
            nm1 = fmaxf(nm1, fmaxf(sacc[j][2], sacc[j][3]));
        }
        nm0 = fmaxf(nm0, __shfl_xor_sync(0xffffffffu, nm0, 1));
        nm0 = fmaxf(nm0, __shfl_xor_sync(0xffffffffu, nm0, 2));
        nm1 = fmaxf(nm1, __shfl_xor_sync(0xffffffffu, nm1, 1));
        nm1 = fmaxf(nm1, __shfl_xor_sync(0xffffffffu, nm1, 2));

        const float c0 = ex2f((m0 - nm0) * cs);
        const float c1 = ex2f((m1 - nm1) * cs);
        m0 = nm0; m1 = nm1;
        l0 *= c0;  l1 *= c1;

#pragma unroll
        for (int j = 0; j < 8; ++j) {
            const float p0 = ex2f((sacc[j][0] - m0) * cs);
            const float p1 = ex2f((sacc[j][1] - m0) * cs);
            const float p2 = ex2f((sacc[j][2] - m1) * cs);
            const float p3 = ex2f((sacc[j][3] - m1) * cs);
            l0 += p0 + p1;
            l1 += p2 + p3;
            sacc[j][0] = p0; sacc[j][1] = p1; sacc[j][2] = p2; sacc[j][3] = p3;
        }
#pragma unroll
        for (int jd = 0; jd < 8; ++jd) {
            oacc[jd][0] *= c0; oacc[jd][1] *= c0;
            oacc[jd][2] *= c1; oacc[jd][3] *= c1;
        }

        // ---- PV: P rounded to fp16 (1 MMA per product) ----
        const int krb = ((lane >> 3) & 1) * 8 + (lane & 7);
        const int dcb = (lane >> 4) * 8;
#pragma unroll
        for (int kk = 0; kk < 4; ++kk) {
            uint32_t pah[4];
            pah[0] = pack2h(sacc[2*kk][0],   sacc[2*kk][1]);
            pah[1] = pack2h(sacc[2*kk][2],   sacc[2*kk][3]);
            pah[2] = pack2h(sacc[2*kk+1][0], sacc[2*kk+1][1]);
            pah[3] = pack2h(sacc[2*kk+1][2], sacc[2*kk+1][3]);
            const int kr = kk * 16 + krb;
#pragma unroll
            for (int jdp = 0; jdp < 4; ++jdp) {
                const int dc = jdp * 16 + dcb;
                const uint32_t off = (uint32_t)(kr * APAD + dc) * 2;
                uint32_t vh[4];
                ldsm4t(vh[0], vh[1], vh[2], vh[3], bVh + off);
                mma_f16(oacc[2*jdp],   pah[0],pah[1],pah[2],pah[3], vh[0],vh[1]);
                mma_f16(oacc[2*jdp+1], pah[0],pah[1],pah[2],pah[3], vh[2],vh[3]);
            }
        }
        __syncthreads();
    }

    // ---- finalize ----
    l0 += __shfl_xor_sync(0xffffffffu, l0, 1);
    l0 += __shfl_xor_sync(0xffffffffu, l0, 2);
    l1 += __shfl_xor_sync(0xffffffffu, l1, 1);
    l1 += __shfl_xor_sync(0xffffffffu, l1, 2);
    const float inv0 = 1.0f / l0;
    const float inv1 = 1.0f / l1;

#pragma unroll
    for (int jd = 0; jd < 8; ++jd) {
        const int col = h * HD + jd * 8 + 2 * t4;
        const size_t w0 = ((qrow0 + g) * E_DIM + col) >> 1;
        const size_t w1 = ((qrow0 + g + 8) * E_DIM + col) >> 1;
        uint32_t hw, lw;
        split2h(oacc[jd][0] * inv0, oacc[jd][1] * inv0, hw, lw);
        reinterpret_cast<uint32_t*>(g_ah)[w0] = hw;
        reinterpret_cast<uint32_t*>(g_al)[w0] = lw;
        split2h(oacc[jd][2] * inv1, oacc[jd][3] * inv1, hw, lw);
        reinterpret_cast<uint32_t*>(g_ah)[w1] = hw;
        reinterpret_cast<uint32_t*>(g_al)[w1] = lw;
    }
}

// ============================================================================
// Launch
// ============================================================================
#define GEMM_SMEM (2 * 3 * GT * 2)   // 61440 bytes

extern "C" void kernel_launch(void* const* d_in, const int* in_sizes, int n_in,
                              void* d_out, int out_size)
{
    const float* x  = (const float*)d_in[0];
    const float* bq = (const float*)d_in[2];
    const float* bk = (const float*)d_in[4];
    const float* bv = (const float*)d_in[6];
    const float* bo = (const float*)d_in[8];
    float* out = (float*)d_out;

    cudaFuncSetAttribute(qkv_kernel,
        cudaFuncAttributeMaxDynamicSharedMemorySize, GEMM_SMEM);
    cudaFuncSetAttribute(outproj_kernel,
        cudaFuncAttributeMaxDynamicSharedMemorySize, GEMM_SMEM);
    cudaFuncSetAttribute(attn_kernel,
        cudaFuncAttributeMaxDynamicSharedMemorySize, ATTN_SMEM);

    // 0) split x (hi/lo) and weights (hi)
    {
        const int total = NELEM + 4 * WELEM;
        split_kernel<<<total / 256, 256>>>(x,
            (const float*)d_in[1], (const float*)d_in[3],
            (const float*)d_in[5], (const float*)d_in[7]);
    }
    // 1) fused QKV projections
    {
        dim3 grid(E_DIM / 128, MAX_M / 128, 3);
        qkv_kernel<<<grid, 256, GEMM_SMEM>>>(bq, bk, bv);
    }
    // 2) flash attention (Q tile 128)
    {
        dim3 grid(S_LEN / 128, 2 * NH);
        attn_kernel<<<grid, 256, ATTN_SMEM>>>();
    }
    // 3) output projection
    {
        dim3 grid(E_DIM / 128, MAX_M / 128);
        outproj_kernel<<<grid, 256, GEMM_SMEM>>>(bo, out);
    }
}

// round 10
// speedup vs baseline: 6.9967x; 1.3637x over previous
#include <cuda_runtime.h>
#include <cuda_fp16.h>
#include <math.h>
#include <stdint.h>

// ============================================================================
// B=2, S=2048, E=1024, H=16, D=64.  M = 4096.
// All matmuls on mma.sync (HMMA; tcgen05 not compilable: ptxas target sm_100).
// Precision plan (error budget vs 1e-3 norm threshold):
//   - QKV projections: plain fp16 (x hi only, W hi only)   [+~1.4e-4 each, linear paths]
//   - QK^T: q,k fp16                                        [scores O(0.3) -> ~1e-4 on P]
//   - PV: P fp16                                            [~1.4e-4]
//   - outproj: A 2-term (ah+al), Wo hi                      [protects final output]
// Predicted total ~2.4e-4.
// (Resubmission of round-9 source: the failure was a container/infra flake —
//  this kernel has no hang-capable constructs.)
// ============================================================================

#define E_DIM 1024
#define NH    16
#define HD    64
#define S_LEN 2048
#define MAX_M 4096
#define NELEM 4194304
#define WELEM 1048576

__device__ __half g_xh[NELEM];
__device__ __half g_wh[4 * WELEM];
__device__ __half g_qh[NELEM];
__device__ __half g_kh[NELEM];
__device__ __half g_vh[NELEM];
__device__ __half g_ah[NELEM], g_al[NELEM];   // attn out hi/lo (outproj A-side)

// ---- helpers ----
__device__ __forceinline__ void mma_f16(float c[4],
    uint32_t a0, uint32_t a1, uint32_t a2, uint32_t a3,
    uint32_t b0, uint32_t b1)
{
    asm volatile(
        "mma.sync.aligned.m16n8k16.row.col.f32.f16.f16.f32 "
        "{%0,%1,%2,%3}, {%4,%5,%6,%7}, {%8,%9}, {%0,%1,%2,%3};"
        : "+f"(c[0]), "+f"(c[1]), "+f"(c[2]), "+f"(c[3])
        : "r"(a0), "r"(a1), "r"(a2), "r"(a3), "r"(b0), "r"(b1));
}

__device__ __forceinline__ float ex2f(float x) {
    float y;
    asm("ex2.approx.ftz.f32 %0, %1;" : "=f"(y) : "f"(x));
    return y;
}

__device__ __forceinline__ void split2h(float x, float y,
                                        uint32_t& hw, uint32_t& lw)
{
    __half hx = __float2half_rn(x);
    __half hy = __float2half_rn(y);
    __half lx = __float2half_rn(x - __half2float(hx));
    __half ly = __float2half_rn(y - __half2float(hy));
    __half2 H = __halves2half2(hx, hy);
    __half2 L = __halves2half2(lx, ly);
    hw = *reinterpret_cast<uint32_t*>(&H);
    lw = *reinterpret_cast<uint32_t*>(&L);
}

__device__ __forceinline__ uint32_t pack2h(float x, float y) {
    __half2 t = __halves2half2(__float2half_rn(x), __float2half_rn(y));
    return *reinterpret_cast<uint32_t*>(&t);
}

__device__ __forceinline__ uint32_t smem_u32(const void* p) {
    return (uint32_t)__cvta_generic_to_shared(p);
}

__device__ __forceinline__ void ldsm4(uint32_t& r0, uint32_t& r1,
                                      uint32_t& r2, uint32_t& r3, uint32_t a) {
    asm volatile("ldmatrix.sync.aligned.m8n8.x4.shared.b16 {%0,%1,%2,%3}, [%4];"
        : "=r"(r0), "=r"(r1), "=r"(r2), "=r"(r3) : "r"(a));
}

__device__ __forceinline__ void ldsm4t(uint32_t& r0, uint32_t& r1,
                                       uint32_t& r2, uint32_t& r3, uint32_t a) {
    asm volatile("ldmatrix.sync.aligned.m8n8.x4.trans.shared.b16 {%0,%1,%2,%3}, [%4];"
        : "=r"(r0), "=r"(r1), "=r"(r2), "=r"(r3) : "r"(a));
}

__device__ __forceinline__ void cp16(uint32_t dst, const void* src) {
    asm volatile("cp.async.cg.shared.global [%0], [%1], 16;"
        :: "r"(dst), "l"(src));
}
#define CP_COMMIT() asm volatile("cp.async.commit_group;")
#define CP_WAIT1()  asm volatile("cp.async.wait_group 1;")
#define CP_WAIT0()  asm volatile("cp.async.wait_group 0;")

// ============================================================================
// Pre-split: x -> fp16, weights -> fp16; outproj-A lo is made by attn kernel.
// float4-vectorized: 4 elements/thread.
// ============================================================================
__global__ __launch_bounds__(256) void split_kernel(
    const float* __restrict__ x,
    const float* __restrict__ Wq, const float* __restrict__ Wk,
    const float* __restrict__ Wv, const float* __restrict__ Wo)
{
    const int i4 = (blockIdx.x * 256 + threadIdx.x) * 4;
    const float* src;
    __half* dst;
    if (i4 < NELEM) {
        src = x + i4;
        dst = g_xh + i4;
    } else {
        const int j4 = i4 - NELEM;
        const int w  = j4 >> 20;
        const int off = j4 & (WELEM - 1);
        const float* W = (w == 0) ? Wq : (w == 1) ? Wk : (w == 2) ? Wv : Wo;
        src = W + off;
        dst = g_wh + j4;
    }
    const float4 v = *reinterpret_cast<const float4*>(src);
    uint2 p;
    p.x = pack2h(v.x, v.y);
    p.y = pack2h(v.z, v.w);
    *reinterpret_cast<uint2*>(dst) = p;
}

// ============================================================================
// fp16 GEMM:  C[m,n] = sum_k A[m,k]*W[n,k] + bias[n]
// BM=128, BN=128, BK=32, 256 thr; cp.async double buffer; ldmatrix.x4.
// HAS_LO: A has a second (lo) operand -> 2 MMAs per product (outproj only).
// OutMode: 0 = fp32 out, 1 = fp16 out.
// ============================================================================
#define GROW 40
#define GT   (128 * GROW)

template<bool HAS_LO, int OutMode>
__device__ __forceinline__ void gemm_core(
    const __half* __restrict__ Ah, const __half* __restrict__ Al,
    const __half* __restrict__ Wh,
    const float* __restrict__ bias,
    float* __restrict__ outF, __half* __restrict__ Oh)
{
    constexpr int NARR = HAS_LO ? 3 : 2;
    extern __shared__ __half sm[];
    const int tid  = threadIdx.x;
    const int lane = tid & 31;
    const int wid  = tid >> 5;
    const int wm   = wid & 3;
    const int wn   = wid >> 2;
    const int g    = lane >> 2;
    const int t4   = lane & 3;
    const int bm   = blockIdx.y * 128;
    const int bn   = blockIdx.x * 128;

    float acc[2][8][4];
#pragma unroll
    for (int s = 0; s < 2; ++s)
#pragma unroll
        for (int j = 0; j < 8; ++j)
#pragma unroll
            for (int e = 0; e < 4; ++e) acc[s][j][e] = 0.0f;

    auto load_stage = [&](int s, int kt) {
#pragma unroll
        for (int i = 0; i < 2 * NARR; ++i) {
            const int a   = i >> 1;               // array index
            const int c   = (i & 1) * 256 + tid;  // [0,512)
            const int row = c >> 2;
            const int col = (c & 3) * 8;
            const __half* base = (a == 0) ? Ah
                               : (HAS_LO ? ((a == 1) ? Al : Wh) : Wh);
            const int rb = (a == NARR - 1) ? bn : bm;
            cp16(smem_u32(sm + (s * NARR + a) * GT + row * GROW + col),
                 base + (size_t)(rb + row) * E_DIM + kt + col);
        }
    };

    load_stage(0, 0);
    CP_COMMIT();

    const int NT = E_DIM / 32;
    for (int t = 0; t < NT; ++t) {
        const int s = t & 1;
        if (t + 1 < NT) {
            load_stage(s ^ 1, (t + 1) * 32);
            CP_COMMIT();
            CP_WAIT1();
        } else {
            CP_WAIT0();
        }
        __syncthreads();

        const uint32_t bAh = smem_u32(sm + (s * NARR + 0) * GT);
        const uint32_t bAl = HAS_LO ? smem_u32(sm + (s * NARR + 1) * GT) : 0u;
        const uint32_t bWh = smem_u32(sm + (s * NARR + NARR - 1) * GT);

#pragma unroll
        for (int kk = 0; kk < 2; ++kk) {
            uint32_t ah[2][4], al[2][4];
            const int ka = kk * 16 + (lane >> 4) * 8;
#pragma unroll
            for (int ss = 0; ss < 2; ++ss) {
                const int m = wm * 32 + ss * 16 + (lane & 15);
                const uint32_t off = (uint32_t)(m * GROW + ka) * 2;
                ldsm4(ah[ss][0], ah[ss][1], ah[ss][2], ah[ss][3], bAh + off);
                if (HAS_LO)
                    ldsm4(al[ss][0], al[ss][1], al[ss][2], al[ss][3], bAl + off);
            }
            const int kb  = kk * 16 + ((lane >> 3) & 1) * 8;
            const int nb0 = (lane & 7) + ((lane >> 4) << 3);
#pragma unroll
            for (int jp = 0; jp < 4; ++jp) {
                const int n = wn * 64 + jp * 16 + nb0;
                const uint32_t off = (uint32_t)(n * GROW + kb) * 2;
                uint32_t bh[4];
                ldsm4(bh[0], bh[1], bh[2], bh[3], bWh + off);
#pragma unroll
                for (int ss = 0; ss < 2; ++ss) {
                    mma_f16(acc[ss][2*jp],   ah[ss][0],ah[ss][1],ah[ss][2],ah[ss][3], bh[0],bh[1]);
                    mma_f16(acc[ss][2*jp+1], ah[ss][0],ah[ss][1],ah[ss][2],ah[ss][3], bh[2],bh[3]);
                    if (HAS_LO) {
                        mma_f16(acc[ss][2*jp],   al[ss][0],al[ss][1],al[ss][2],al[ss][3], bh[0],bh[1]);
                        mma_f16(acc[ss][2*jp+1], al[ss][0],al[ss][1],al[ss][2],al[ss][3], bh[2],bh[3]);
                    }
                }
            }
        }
        __syncthreads();
    }

    // epilogue
#pragma unroll
    for (int j = 0; j < 8; ++j) {
        const int col = bn + wn * 64 + j * 8 + 2 * t4;
        const float b0 = bias[col], b1 = bias[col + 1];
#pragma unroll
        for (int ss = 0; ss < 2; ++ss) {
            const int r0 = bm + wm * 32 + ss * 16 + g;
            const float v0 = acc[ss][j][0] + b0, v1 = acc[ss][j][1] + b1;
            const float v2 = acc[ss][j][2] + b0, v3 = acc[ss][j][3] + b1;
            const size_t w0 = ((size_t)r0 * E_DIM + col) >> 1;
            const size_t w1 = ((size_t)(r0 + 8) * E_DIM + col) >> 1;
            if (OutMode == 1) {
                reinterpret_cast<uint32_t*>(Oh)[w0] = pack2h(v0, v1);
                reinterpret_cast<uint32_t*>(Oh)[w1] = pack2h(v2, v3);
            } else {
                float2 p0; p0.x = v0; p0.y = v1;
                float2 p1; p1.x = v2; p1.y = v3;
                *reinterpret_cast<float2*>(outF + (size_t)r0 * E_DIM + col) = p0;
                *reinterpret_cast<float2*>(outF + (size_t)(r0 + 8) * E_DIM + col) = p1;
            }
        }
    }
}

__global__ __launch_bounds__(256, 2) void qkv_kernel(
    const float* __restrict__ bq, const float* __restrict__ bk,
    const float* __restrict__ bv)
{
    const int z = blockIdx.z;
    const __half* Wh = g_wh + (size_t)z * WELEM;
    const float* bias = (z == 0) ? bq : (z == 1) ? bk : bv;
    __half* Oh = (z == 0) ? g_qh : (z == 1) ? g_kh : g_vh;
    gemm_core<false, 1>(g_xh, nullptr, Wh, bias, nullptr, Oh);
}

__global__ __launch_bounds__(256, 2) void outproj_kernel(
    const float* __restrict__ bo, float* __restrict__ out)
{
    gemm_core<true, 0>(g_ah, g_al, g_wh + (size_t)3 * WELEM, bo, out, nullptr);
}

// ============================================================================
// Flash attention: 256 thr (8 warps), Q tile 128, K tiles of 64.
// QK^T: 1 MMA (q,k fp16).  PV: 1 MMA (P fp16).  Out stored hi+lo.
// ============================================================================
#define APAD 72
#define AT   (64 * APAD)
#define ATTN_SMEM (2 * 2 * AT * 2)   // 36864 B

__global__ __launch_bounds__(256) void attn_kernel()
{
    extern __shared__ __half sm[];
    const int tid  = threadIdx.x;
    const int lane = tid & 31;
    const int wid  = tid >> 5;          // 0..7
    const int g    = lane >> 2;
    const int t4   = lane & 3;

    const int bh = blockIdx.y;
    const int b  = bh >> 4;
    const int h  = bh & 15;
    const int q0 = blockIdx.x * 128 + wid * 16;
    const size_t qrow0 = (size_t)(b * S_LEN + q0);

    const float cs = 0.18033688011112042f;   // (1/8) * log2(e)

    uint32_t qfh[4][4];
#pragma unroll
    for (int kk = 0; kk < 4; ++kk) {
        const size_t i0 = (qrow0 + g) * E_DIM + h * HD + kk * 16 + 2 * t4;
        const size_t i1 = (qrow0 + g + 8) * E_DIM + h * HD + kk * 16 + 2 * t4;
        qfh[kk][0] = *reinterpret_cast<const uint32_t*>(g_qh + i0);
        qfh[kk][1] = *reinterpret_cast<const uint32_t*>(g_qh + i1);
        qfh[kk][2] = *reinterpret_cast<const uint32_t*>(g_qh + i0 + 8);
        qfh[kk][3] = *reinterpret_cast<const uint32_t*>(g_qh + i1 + 8);
    }

    float oacc[8][4];
#pragma unroll
    for (int jd = 0; jd < 8; ++jd)
#pragma unroll
        for (int e = 0; e < 4; ++e) oacc[jd][e] = 0.0f;
    float m0 = -INFINITY, m1 = -INFINITY, l0 = 0.0f, l1 = 0.0f;

    auto load_stage = [&](int s, int kt) {
#pragma unroll
        for (int i = 0; i < 4; ++i) {
            const int idx = i * 256 + tid;       // [0, 1024)
            const int a   = idx >> 9;            // 0:Kh 1:Vh
            const int rem = idx & 511;
            const int row = rem >> 3;            // 0..63
            const int col = (rem & 7) * 8;
            const __half* base = (a == 0) ? g_kh : g_vh;
            cp16(smem_u32(sm + (s * 2 + a) * AT + row * APAD + col),
                 base + (size_t)(b * S_LEN + kt * 64 + row) * E_DIM + h * HD + col);
        }
    };

    load_stage(0, 0);
    CP_COMMIT();

    const int NT = S_LEN / 64;
    for (int t = 0; t < NT; ++t) {
        const int s = t & 1;
        if (t + 1 < NT) {
            load_stage(s ^ 1, t + 1);
            CP_COMMIT();
            CP_WAIT1();
        } else {
            CP_WAIT0();
        }
        __syncthreads();

        const uint32_t bKh = smem_u32(sm + (s * 2 + 0) * AT);
        const uint32_t bVh = smem_u32(sm + (s * 2 + 1) * AT);

        // ---- QK^T (1-term) ----
        float sacc[8][4];
#pragma unroll
        for (int j = 0; j < 8; ++j)
#pragma unroll
            for (int e = 0; e < 4; ++e) sacc[j][e] = 0.0f;

        const int nb0 = (lane & 7) + ((lane >> 4) << 3);
        const int kb0 = ((lane >> 3) & 1) * 8;
#pragma unroll
        for (int jp = 0; jp < 4; ++jp) {
            const int n = jp * 16 + nb0;
#pragma unroll
            for (int kk = 0; kk < 4; ++kk) {
                const uint32_t off = (uint32_t)(n * APAD + kk * 16 + kb0) * 2;
                uint32_t kh[4];
                ldsm4(kh[0], kh[1], kh[2], kh[3], bKh + off);
                mma_f16(sacc[2*jp],   qfh[kk][0],qfh[kk][1],qfh[kk][2],qfh[kk][3], kh[0],kh[1]);
                mma_f16(sacc[2*jp+1], qfh[kk][0],qfh[kk][1],qfh[kk][2],qfh[kk][3], kh[2],kh[3]);
            }
        }

        // ---- online softmax ----
        float nm0 = m0, nm1 = m1;
#pragma unroll
        for (int j = 0; j < 8; ++j) {
            nm0 = fmaxf(nm0, fmaxf(sacc[j][0], sacc[j][1]));
            nm1 = fmaxf(nm1, fmaxf(sacc[j][2], sacc[j][3]));
        }
        nm0 = fmaxf(nm0, __shfl_xor_sync(0xffffffffu, nm0, 1));
        nm0 = fmaxf(nm0, __shfl_xor_sync(0xffffffffu, nm0, 2));
        nm1 = fmaxf(nm1, __shfl_xor_sync(0xffffffffu, nm1, 1));
        nm1 = fmaxf(nm1, __shfl_xor_sync(0xffffffffu, nm1, 2));

        const float c0 = ex2f((m0 - nm0) * cs);
        const float c1 = ex2f((m1 - nm1) * cs);
        m0 = nm0; m1 = nm1;
        l0 *= c0;  l1 *= c1;

#pragma unroll
        for (int j = 0; j < 8; ++j) {
            const float p0 = ex2f((sacc[j][0] - m0) * cs);
            const float p1 = ex2f((sacc[j][1] - m0) * cs);
            const float p2 = ex2f((sacc[j][2] - m1) * cs);
            const float p3 = ex2f((sacc[j][3] - m1) * cs);
            l0 += p0 + p1;
            l1 += p2 + p3;
            sacc[j][0] = p0; sacc[j][1] = p1; sacc[j][2] = p2; sacc[j][3] = p3;
        }
#pragma unroll
        for (int jd = 0; jd < 8; ++jd) {
            oacc[jd][0] *= c0; oacc[jd][1] *= c0;
            oacc[jd][2] *= c1; oacc[jd][3] *= c1;
        }

        // ---- PV (P fp16) ----
        const int krb = ((lane >> 3) & 1) * 8 + (lane & 7);
        const int dcb = (lane >> 4) * 8;
#pragma unroll
        for (int kk = 0; kk < 4; ++kk) {
            uint32_t pah[4];
            pah[0] = pack2h(sacc[2*kk][0],   sacc[2*kk][1]);
            pah[1] = pack2h(sacc[2*kk][2],   sacc[2*kk][3]);
            pah[2] = pack2h(sacc[2*kk+1][0], sacc[2*kk+1][1]);
            pah[3] = pack2h(sacc[2*kk+1][2], sacc[2*kk+1][3]);
            const int kr = kk * 16 + krb;
#pragma unroll
            for (int jdp = 0; jdp < 4; ++jdp) {
                const int dc = jdp * 16 + dcb;
                const uint32_t off = (uint32_t)(kr * APAD + dc) * 2;
                uint32_t vh[4];
                ldsm4t(vh[0], vh[1], vh[2], vh[3], bVh + off);
                mma_f16(oacc[2*jdp],   pah[0],pah[1],pah[2],pah[3], vh[0],vh[1]);
                mma_f16(oacc[2*jdp+1], pah[0],pah[1],pah[2],pah[3], vh[2],vh[3]);
            }
        }
        __syncthreads();
    }

    // ---- finalize: store hi+lo for outproj's 2-term A ----
    l0 += __shfl_xor_sync(0xffffffffu, l0, 1);
    l0 += __shfl_xor_sync(0xffffffffu, l0, 2);
    l1 += __shfl_xor_sync(0xffffffffu, l1, 1);
    l1 += __shfl_xor_sync(0xffffffffu, l1, 2);
    const float inv0 = 1.0f / l0;
    const float inv1 = 1.0f / l1;

#pragma unroll
    for (int jd = 0; jd < 8; ++jd) {
        const int col = h * HD + jd * 8 + 2 * t4;
        const size_t w0 = ((qrow0 + g) * E_DIM + col) >> 1;
        const size_t w1 = ((qrow0 + g + 8) * E_DIM + col) >> 1;
        uint32_t hw, lw;
        split2h(oacc[jd][0] * inv0, oacc[jd][1] * inv0, hw, lw);
        reinterpret_cast<uint32_t*>(g_ah)[w0] = hw;
        reinterpret_cast<uint32_t*>(g_al)[w0] = lw;
        split2h(oacc[jd][2] * inv1, oacc[jd][3] * inv1, hw, lw);
        reinterpret_cast<uint32_t*>(g_ah)[w1] = hw;
        reinterpret_cast<uint32_t*>(g_al)[w1] = lw;
    }
}

// ============================================================================
// Launch
// ============================================================================
#define GEMM_SMEM2 (2 * 2 * GT * 2)   // 40960 bytes (qkv)
#define GEMM_SMEM3 (2 * 3 * GT * 2)   // 61440 bytes (outproj)

extern "C" void kernel_launch(void* const* d_in, const int* in_sizes, int n_in,
                              void* d_out, int out_size)
{
    const float* x  = (const float*)d_in[0];
    const float* bq = (const float*)d_in[2];
    const float* bk = (const float*)d_in[4];
    const float* bv = (const float*)d_in[6];
    const float* bo = (const float*)d_in[8];
    float* out = (float*)d_out;

    cudaFuncSetAttribute(qkv_kernel,
        cudaFuncAttributeMaxDynamicSharedMemorySize, GEMM_SMEM2);
    cudaFuncSetAttribute(outproj_kernel,
        cudaFuncAttributeMaxDynamicSharedMemorySize, GEMM_SMEM3);
    cudaFuncSetAttribute(attn_kernel,
        cudaFuncAttributeMaxDynamicSharedMemorySize, ATTN_SMEM);

    // 0) convert x and weights to fp16 (vectorized x4)
    {
        const int total = (NELEM + 4 * WELEM) / 4;
        split_kernel<<<total / 256, 256>>>(x,
            (const float*)d_in[1], (const float*)d_in[3],
            (const float*)d_in[5], (const float*)d_in[7]);
    }
    // 1) fused QKV projections (1-term fp16)
    {
        dim3 grid(E_DIM / 128, MAX_M / 128, 3);
        qkv_kernel<<<grid, 256, GEMM_SMEM2>>>(bq, bk, bv);
    }
    // 2) flash attention (Q tile 128, 1-term QK/PV)
    {
        dim3 grid(S_LEN / 128, 2 * NH);
        attn_kernel<<<grid, 256, ATTN_SMEM>>>();
    }
    // 3) output projection (2-term A)
    {
        dim3 grid(E_DIM / 128, MAX_M / 128);
        outproj_kernel<<<grid, 256, GEMM_SMEM3>>>(bo, out);
    }
}

// round 11
// speedup vs baseline: 8.2797x; 1.1834x over previous
#include <cuda_runtime.h>
#include <cuda_fp16.h>
#include <math.h>
#include <stdint.h>

// ============================================================================
// B=2, S=2048, E=1024, H=16, D=64.  M = 4096.
// All matmuls 1-term fp16 on mma.sync (HMMA; tcgen05 not compilable here).
// Error budget (measured 1.98e-4 before outproj-lo drop; predicted ~2.8e-4).
// GEMM: BK=64 chunks (16 sync iterations instead of 32).
// ============================================================================

#define E_DIM 1024
#define NH    16
#define HD    64
#define S_LEN 2048
#define MAX_M 4096
#define NELEM 4194304
#define WELEM 1048576

__device__ __half g_xh[NELEM];
__device__ __half g_wh[4 * WELEM];
__device__ __half g_qh[NELEM];
__device__ __half g_kh[NELEM];
__device__ __half g_vh[NELEM];
__device__ __half g_ah[NELEM];     // attention output (fp16), outproj A-side

// ---- helpers ----
__device__ __forceinline__ void mma_f16(float c[4],
    uint32_t a0, uint32_t a1, uint32_t a2, uint32_t a3,
    uint32_t b0, uint32_t b1)
{
    asm volatile(
        "mma.sync.aligned.m16n8k16.row.col.f32.f16.f16.f32 "
        "{%0,%1,%2,%3}, {%4,%5,%6,%7}, {%8,%9}, {%0,%1,%2,%3};"
        : "+f"(c[0]), "+f"(c[1]), "+f"(c[2]), "+f"(c[3])
        : "r"(a0), "r"(a1), "r"(a2), "r"(a3), "r"(b0), "r"(b1));
}

__device__ __forceinline__ float ex2f(float x) {
    float y;
    asm("ex2.approx.ftz.f32 %0, %1;" : "=f"(y) : "f"(x));
    return y;
}

__device__ __forceinline__ uint32_t pack2h(float x, float y) {
    __half2 t = __halves2half2(__float2half_rn(x), __float2half_rn(y));
    return *reinterpret_cast<uint32_t*>(&t);
}

__device__ __forceinline__ uint32_t smem_u32(const void* p) {
    return (uint32_t)__cvta_generic_to_shared(p);
}

__device__ __forceinline__ void ldsm4(uint32_t& r0, uint32_t& r1,
                                      uint32_t& r2, uint32_t& r3, uint32_t a) {
    asm volatile("ldmatrix.sync.aligned.m8n8.x4.shared.b16 {%0,%1,%2,%3}, [%4];"
        : "=r"(r0), "=r"(r1), "=r"(r2), "=r"(r3) : "r"(a));
}

__device__ __forceinline__ void ldsm4t(uint32_t& r0, uint32_t& r1,
                                       uint32_t& r2, uint32_t& r3, uint32_t a) {
    asm volatile("ldmatrix.sync.aligned.m8n8.x4.trans.shared.b16 {%0,%1,%2,%3}, [%4];"
        : "=r"(r0), "=r"(r1), "=r"(r2), "=r"(r3) : "r"(a));
}

__device__ __forceinline__ void cp16(uint32_t dst, const void* src) {
    asm volatile("cp.async.cg.shared.global [%0], [%1], 16;"
        :: "r"(dst), "l"(src));
}
#define CP_COMMIT() asm volatile("cp.async.commit_group;")
#define CP_WAIT1()  asm volatile("cp.async.wait_group 1;")
#define CP_WAIT0()  asm volatile("cp.async.wait_group 0;")

// ============================================================================
// Convert: x and 4 weight matrices -> fp16 (float4-vectorized)
// ============================================================================
__global__ __launch_bounds__(256) void split_kernel(
    const float* __restrict__ x,
    const float* __restrict__ Wq, const float* __restrict__ Wk,
    const float* __restrict__ Wv, const float* __restrict__ Wo)
{
    const int i4 = (blockIdx.x * 256 + threadIdx.x) * 4;
    const float* src;
    __half* dst;
    if (i4 < NELEM) {
        src = x + i4;
        dst = g_xh + i4;
    } else {
        const int j4 = i4 - NELEM;
        const int w  = j4 >> 20;
        const int off = j4 & (WELEM - 1);
        const float* W = (w == 0) ? Wq : (w == 1) ? Wk : (w == 2) ? Wv : Wo;
        src = W + off;
        dst = g_wh + j4;
    }
    const float4 v = *reinterpret_cast<const float4*>(src);
    uint2 p;
    p.x = pack2h(v.x, v.y);
    p.y = pack2h(v.z, v.w);
    *reinterpret_cast<uint2*>(dst) = p;
}

// ============================================================================
// fp16 GEMM:  C[m,n] = sum_k A[m,k]*W[n,k] + bias[n]
// BM=128, BN=128, BK=64, 256 thr (4m x 2n warps, warp tile 32x64).
// cp.async double buffer; ldmatrix.x4; row stride 72 halves (144B).
// OutMode: 0 = fp32 out, 1 = fp16 out.
// ============================================================================
#define GROW 72
#define GT   (128 * GROW)      // halves per array per stage

template<int OutMode>
__device__ __forceinline__ void gemm_core(
    const __half* __restrict__ Ah, const __half* __restrict__ Wh,
    const float* __restrict__ bias,
    float* __restrict__ outF, __half* __restrict__ Oh)
{
    extern __shared__ __half sm[];
    const int tid  = threadIdx.x;
    const int lane = tid & 31;
    const int wid  = tid >> 5;
    const int wm   = wid & 3;
    const int wn   = wid >> 2;
    const int g    = lane >> 2;
    const int t4   = lane & 3;
    const int bm   = blockIdx.y * 128;
    const int bn   = blockIdx.x * 128;

    float acc[2][8][4];
#pragma unroll
    for (int s = 0; s < 2; ++s)
#pragma unroll
        for (int j = 0; j < 8; ++j)
#pragma unroll
            for (int e = 0; e < 4; ++e) acc[s][j][e] = 0.0f;

    // stage: 2 arrays x 128 rows x 64 halves; 2048 cp16; 8 per thread
    auto load_stage = [&](int s, int kt) {
#pragma unroll
        for (int i = 0; i < 8; ++i) {
            const int idx = i * 256 + tid;        // [0, 2048)
            const int a   = idx >> 10;            // 0:A 1:W
            const int rem = idx & 1023;
            const int row = rem >> 3;             // 0..127
            const int col = (rem & 7) * 8;        // 0..56
            const __half* base = (a == 0) ? Ah : Wh;
            const int rb = (a == 0) ? bm : bn;
            cp16(smem_u32(sm + (s * 2 + a) * GT + row * GROW + col),
                 base + (size_t)(rb + row) * E_DIM + kt + col);
        }
    };

    load_stage(0, 0);
    CP_COMMIT();

    const int NT = E_DIM / 64;   // 16
    for (int t = 0; t < NT; ++t) {
        const int s = t & 1;
        if (t + 1 < NT) {
            load_stage(s ^ 1, (t + 1) * 64);
            CP_COMMIT();
            CP_WAIT1();
        } else {
            CP_WAIT0();
        }
        __syncthreads();

        const uint32_t bAh = smem_u32(sm + (s * 2 + 0) * GT);
        const uint32_t bWh = smem_u32(sm + (s * 2 + 1) * GT);

#pragma unroll
        for (int kk = 0; kk < 4; ++kk) {
            uint32_t ah[2][4];
            const int ka = kk * 16 + (lane >> 4) * 8;
#pragma unroll
            for (int ss = 0; ss < 2; ++ss) {
                const int m = wm * 32 + ss * 16 + (lane & 15);
                const uint32_t off = (uint32_t)(m * GROW + ka) * 2;
                ldsm4(ah[ss][0], ah[ss][1], ah[ss][2], ah[ss][3], bAh + off);
            }
            const int kb  = kk * 16 + ((lane >> 3) & 1) * 8;
            const int nb0 = (lane & 7) + ((lane >> 4) << 3);
#pragma unroll
            for (int jp = 0; jp < 4; ++jp) {
                const int n = wn * 64 + jp * 16 + nb0;
                const uint32_t off = (uint32_t)(n * GROW + kb) * 2;
                uint32_t bh[4];
                ldsm4(bh[0], bh[1], bh[2], bh[3], bWh + off);
#pragma unroll
                for (int ss = 0; ss < 2; ++ss) {
                    mma_f16(acc[ss][2*jp],   ah[ss][0],ah[ss][1],ah[ss][2],ah[ss][3], bh[0],bh[1]);
                    mma_f16(acc[ss][2*jp+1], ah[ss][0],ah[ss][1],ah[ss][2],ah[ss][3], bh[2],bh[3]);
                }
            }
        }
        __syncthreads();
    }

    // epilogue
#pragma unroll
    for (int j = 0; j < 8; ++j) {
        const int col = bn + wn * 64 + j * 8 + 2 * t4;
        const float b0 = bias[col], b1 = bias[col + 1];
#pragma unroll
        for (int ss = 0; ss < 2; ++ss) {
            const int r0 = bm + wm * 32 + ss * 16 + g;
            const float v0 = acc[ss][j][0] + b0, v1 = acc[ss][j][1] + b1;
            const float v2 = acc[ss][j][2] + b0, v3 = acc[ss][j][3] + b1;
            const size_t w0 = ((size_t)r0 * E_DIM + col) >> 1;
            const size_t w1 = ((size_t)(r0 + 8) * E_DIM + col) >> 1;
            if (OutMode == 1) {
                reinterpret_cast<uint32_t*>(Oh)[w0] = pack2h(v0, v1);
                reinterpret_cast<uint32_t*>(Oh)[w1] = pack2h(v2, v3);
            } else {
                float2 p0; p0.x = v0; p0.y = v1;
                float2 p1; p1.x = v2; p1.y = v3;
                *reinterpret_cast<float2*>(outF + (size_t)r0 * E_DIM + col) = p0;
                *reinterpret_cast<float2*>(outF + (size_t)(r0 + 8) * E_DIM + col) = p1;
            }
        }
    }
}

__global__ __launch_bounds__(256, 2) void qkv_kernel(
    const float* __restrict__ bq, const float* __restrict__ bk,
    const float* __restrict__ bv)
{
    const int z = blockIdx.z;
    const __half* Wh = g_wh + (size_t)z * WELEM;
    const float* bias = (z == 0) ? bq : (z == 1) ? bk : bv;
    __half* Oh = (z == 0) ? g_qh : (z == 1) ? g_kh : g_vh;
    gemm_core<1>(g_xh, Wh, bias, nullptr, Oh);
}

__global__ __launch_bounds__(256, 2) void outproj_kernel(
    const float* __restrict__ bo, float* __restrict__ out)
{
    gemm_core<0>(g_ah, g_wh + (size_t)3 * WELEM, bo, out, nullptr);
}

// ============================================================================
// Flash attention: 256 thr (8 warps), Q tile 128, K tiles of 64.
// QK^T: 1 MMA (q,k fp16).  PV: 1 MMA (P fp16).  Output stored fp16 (hi only).
// ============================================================================
#define APAD 72
#define AT   (64 * APAD)
#define ATTN_SMEM (2 * 2 * AT * 2)   // 36864 B

__global__ __launch_bounds__(256) void attn_kernel()
{
    extern __shared__ __half sm[];
    const int tid  = threadIdx.x;
    const int lane = tid & 31;
    const int wid  = tid >> 5;          // 0..7
    const int g    = lane >> 2;
    const int t4   = lane & 3;

    const int bh = blockIdx.y;
    const int b  = bh >> 4;
    const int h  = bh & 15;
    const int q0 = blockIdx.x * 128 + wid * 16;
    const size_t qrow0 = (size_t)(b * S_LEN + q0);

    const float cs = 0.18033688011112042f;   // (1/8) * log2(e)

    uint32_t qfh[4][4];
#pragma unroll
    for (int kk = 0; kk < 4; ++kk) {
        const size_t i0 = (qrow0 + g) * E_DIM + h * HD + kk * 16 + 2 * t4;
        const size_t i1 = (qrow0 + g + 8) * E_DIM + h * HD + kk * 16 + 2 * t4;
        qfh[kk][0] = *reinterpret_cast<const uint32_t*>(g_qh + i0);
        qfh[kk][1] = *reinterpret_cast<const uint32_t*>(g_qh + i1);
        qfh[kk][2] = *reinterpret_cast<const uint32_t*>(g_qh + i0 + 8);
        qfh[kk][3] = *reinterpret_cast<const uint32_t*>(g_qh + i1 + 8);
    }

    float oacc[8][4];
#pragma unroll
    for (int jd = 0; jd < 8; ++jd)
#pragma unroll
        for (int e = 0; e < 4; ++e) oacc[jd][e] = 0.0f;
    float m0 = -INFINITY, m1 = -INFINITY, l0 = 0.0f, l1 = 0.0f;

    auto load_stage = [&](int s, int kt) {
#pragma unroll
        for (int i = 0; i < 4; ++i) {
            const int idx = i * 256 + tid;       // [0, 1024)
            const int a   = idx >> 9;            // 0:Kh 1:Vh
            const int rem = idx & 511;
            const int row = rem >> 3;            // 0..63
            const int col = (rem & 7) * 8;
            const __half* base = (a == 0) ? g_kh : g_vh;
            cp16(smem_u32(sm + (s * 2 + a) * AT + row * APAD + col),
                 base + (size_t)(b * S_LEN + kt * 64 + row) * E_DIM + h * HD + col);
        }
    };

    load_stage(0, 0);
    CP_COMMIT();

    const int NT = S_LEN / 64;
    for (int t = 0; t < NT; ++t) {
        const int s = t & 1;
        if (t + 1 < NT) {
            load_stage(s ^ 1, t + 1);
            CP_COMMIT();
            CP_WAIT1();
        } else {
            CP_WAIT0();
        }
        __syncthreads();

        const uint32_t bKh = smem_u32(sm + (s * 2 + 0) * AT);
        const uint32_t bVh = smem_u32(sm + (s * 2 + 1) * AT);

        // ---- QK^T ----
        float sacc[8][4];
#pragma unroll
        for (int j = 0; j < 8; ++j)
#pragma unroll
            for (int e = 0; e < 4; ++e) sacc[j][e] = 0.0f;

        const int nb0 = (lane & 7) + ((lane >> 4) << 3);
        const int kb0 = ((lane >> 3) & 1) * 8;
#pragma unroll
        for (int jp = 0; jp < 4; ++jp) {
            const int n = jp * 16 + nb0;
#pragma unroll
            for (int kk = 0; kk < 4; ++kk) {
                const uint32_t off = (uint32_t)(n * APAD + kk * 16 + kb0) * 2;
                uint32_t kh[4];
                ldsm4(kh[0], kh[1], kh[2], kh[3], bKh + off);
                mma_f16(sacc[2*jp],   qfh[kk][0],qfh[kk][1],qfh[kk][2],qfh[kk][3], kh[0],kh[1]);
                mma_f16(sacc[2*jp+1], qfh[kk][0],qfh[kk][1],qfh[kk][2],qfh[kk][3], kh[2],kh[3]);
            }
        }

        // ---- online softmax ----
        float nm0 = m0, nm1 = m1;
#pragma unroll
        for (int j = 0; j < 8; ++j) {
            nm0 = fmaxf(nm0, fmaxf(sacc[j][0], sacc[j][1]));
            nm1 = fmaxf(nm1, fmaxf(sacc[j][2], sacc[j][3]));
        }
        nm0 = fmaxf(nm0, __shfl_xor_sync(0xffffffffu, nm0, 1));
        nm0 = fmaxf(nm0, __shfl_xor_sync(0xffffffffu, nm0, 2));
        nm1 = fmaxf(nm1, __shfl_xor_sync(0xffffffffu, nm1, 1));
        nm1 = fmaxf(nm1, __shfl_xor_sync(0xffffffffu, nm1, 2));

        const float c0 = ex2f((m0 - nm0) * cs);
        const float c1 = ex2f((m1 - nm1) * cs);
        m0 = nm0; m1 = nm1;
        l0 *= c0;  l1 *= c1;

#pragma unroll
        for (int j = 0; j < 8; ++j) {
            const float p0 = ex2f((sacc[j][0] - m0) * cs);
            const float p1 = ex2f((sacc[j][1] - m0) * cs);
            const float p2 = ex2f((sacc[j][2] - m1) * cs);
            const float p3 = ex2f((sacc[j][3] - m1) * cs);
            l0 += p0 + p1;
            l1 += p2 + p3;
            sacc[j][0] = p0; sacc[j][1] = p1; sacc[j][2] = p2; sacc[j][3] = p3;
        }
#pragma unroll
        for (int jd = 0; jd < 8; ++jd) {
            oacc[jd][0] *= c0; oacc[jd][1] *= c0;
            oacc[jd][2] *= c1; oacc[jd][3] *= c1;
        }

        // ---- PV ----
        const int krb = ((lane >> 3) & 1) * 8 + (lane & 7);
        const int dcb = (lane >> 4) * 8;
#pragma unroll
        for (int kk = 0; kk < 4; ++kk) {
            uint32_t pah[4];
            pah[0] = pack2h(sacc[2*kk][0],   sacc[2*kk][1]);
            pah[1] = pack2h(sacc[2*kk][2],   sacc[2*kk][3]);
            pah[2] = pack2h(sacc[2*kk+1][0], sacc[2*kk+1][1]);
            pah[3] = pack2h(sacc[2*kk+1][2], sacc[2*kk+1][3]);
            const int kr = kk * 16 + krb;
#pragma unroll
            for (int jdp = 0; jdp < 4; ++jdp) {
                const int dc = jdp * 16 + dcb;
                const uint32_t off = (uint32_t)(kr * APAD + dc) * 2;
                uint32_t vh[4];
                ldsm4t(vh[0], vh[1], vh[2], vh[3], bVh + off);
                mma_f16(oacc[2*jdp],   pah[0],pah[1],pah[2],pah[3], vh[0],vh[1]);
                mma_f16(oacc[2*jdp+1], pah[0],pah[1],pah[2],pah[3], vh[2],vh[3]);
            }
        }
        __syncthreads();
    }

    // ---- finalize: fp16 output ----
    l0 += __shfl_xor_sync(0xffffffffu, l0, 1);
    l0 += __shfl_xor_sync(0xffffffffu, l0, 2);
    l1 += __shfl_xor_sync(0xffffffffu, l1, 1);
    l1 += __shfl_xor_sync(0xffffffffu, l1, 2);
    const float inv0 = 1.0f / l0;
    const float inv1 = 1.0f / l1;

#pragma unroll
    for (int jd = 0; jd < 8; ++jd) {
        const int col = h * HD + jd * 8 + 2 * t4;
        const size_t w0 = ((qrow0 + g) * E_DIM + col) >> 1;
        const size_t w1 = ((qrow0 + g + 8) * E_DIM + col) >> 1;
        reinterpret_cast<uint32_t*>(g_ah)[w0] =
            pack2h(oacc[jd][0] * inv0, oacc[jd][1] * inv0);
        reinterpret_cast<uint32_t*>(g_ah)[w1] =
            pack2h(oacc[jd][2] * inv1, oacc[jd][3] * inv1);
    }
}

// ============================================================================
// Launch
// ============================================================================
#define GEMM_SMEM (2 * 2 * GT * 2)   // 73728 bytes

extern "C" void kernel_launch(void* const* d_in, const int* in_sizes, int n_in,
                              void* d_out, int out_size)
{
    const float* x  = (const float*)d_in[0];
    const float* bq = (const float*)d_in[2];
    const float* bk = (const float*)d_in[4];
    const float* bv = (const float*)d_in[6];
    const float* bo = (const float*)d_in[8];
    float* out = (float*)d_out;

    cudaFuncSetAttribute(qkv_kernel,
        cudaFuncAttributeMaxDynamicSharedMemorySize, GEMM_SMEM);
    cudaFuncSetAttribute(outproj_kernel,
        cudaFuncAttributeMaxDynamicSharedMemorySize, GEMM_SMEM);
    cudaFuncSetAttribute(attn_kernel,
        cudaFuncAttributeMaxDynamicSharedMemorySize, ATTN_SMEM);

    // 0) convert x and weights to fp16
    {
        const int total = (NELEM + 4 * WELEM) / 4;
        split_kernel<<<total / 256, 256>>>(x,
            (const float*)d_in[1], (const float*)d_in[3],
            (const float*)d_in[5], (const float*)d_in[7]);
    }
    // 1) fused QKV projections
    {
        dim3 grid(E_DIM / 128, MAX_M / 128, 3);
        qkv_kernel<<<grid, 256, GEMM_SMEM>>>(bq, bk, bv);
    }
    // 2) flash attention
    {
        dim3 grid(S_LEN / 128, 2 * NH);
        attn_kernel<<<grid, 256, ATTN_SMEM>>>();
    }
    // 3) output projection
    {
        dim3 grid(E_DIM / 128, MAX_M / 128);
        outproj_kernel<<<grid, 256, GEMM_SMEM>>>(bo, out);
    }
}

// round 12
// speedup vs baseline: 8.4723x; 1.0233x over previous
#include <cuda_runtime.h>
#include <cuda_fp16.h>
#include <math.h>
#include <stdint.h>

// ============================================================================
// B=2, S=2048, E=1024, H=16, D=64.  M = 4096.
// All matmuls 1-term fp16 on mma.sync (HMMA; tcgen05 not compilable here).
// This round: single-__syncthreads-per-iteration pipelines (wait -> sync ->
// issue-next -> compute) in both GEMM and attention mainloops.
// ============================================================================

#define E_DIM 1024
#define NH    16
#define HD    64
#define S_LEN 2048
#define MAX_M 4096
#define NELEM 4194304
#define WELEM 1048576

__device__ __half g_xh[NELEM];
__device__ __half g_wh[4 * WELEM];
__device__ __half g_qh[NELEM];
__device__ __half g_kh[NELEM];
__device__ __half g_vh[NELEM];
__device__ __half g_ah[NELEM];     // attention output (fp16), outproj A-side

// ---- helpers ----
__device__ __forceinline__ void mma_f16(float c[4],
    uint32_t a0, uint32_t a1, uint32_t a2, uint32_t a3,
    uint32_t b0, uint32_t b1)
{
    asm volatile(
        "mma.sync.aligned.m16n8k16.row.col.f32.f16.f16.f32 "
        "{%0,%1,%2,%3}, {%4,%5,%6,%7}, {%8,%9}, {%0,%1,%2,%3};"
        : "+f"(c[0]), "+f"(c[1]), "+f"(c[2]), "+f"(c[3])
        : "r"(a0), "r"(a1), "r"(a2), "r"(a3), "r"(b0), "r"(b1));
}

__device__ __forceinline__ float ex2f(float x) {
    float y;
    asm("ex2.approx.ftz.f32 %0, %1;" : "=f"(y) : "f"(x));
    return y;
}

__device__ __forceinline__ uint32_t pack2h(float x, float y) {
    __half2 t = __halves2half2(__float2half_rn(x), __float2half_rn(y));
    return *reinterpret_cast<uint32_t*>(&t);
}

__device__ __forceinline__ uint32_t smem_u32(const void* p) {
    return (uint32_t)__cvta_generic_to_shared(p);
}

__device__ __forceinline__ void ldsm4(uint32_t& r0, uint32_t& r1,
                                      uint32_t& r2, uint32_t& r3, uint32_t a) {
    asm volatile("ldmatrix.sync.aligned.m8n8.x4.shared.b16 {%0,%1,%2,%3}, [%4];"
        : "=r"(r0), "=r"(r1), "=r"(r2), "=r"(r3) : "r"(a));
}

__device__ __forceinline__ void ldsm4t(uint32_t& r0, uint32_t& r1,
                                       uint32_t& r2, uint32_t& r3, uint32_t a) {
    asm volatile("ldmatrix.sync.aligned.m8n8.x4.trans.shared.b16 {%0,%1,%2,%3}, [%4];"
        : "=r"(r0), "=r"(r1), "=r"(r2), "=r"(r3) : "r"(a));
}

__device__ __forceinline__ void cp16(uint32_t dst, const void* src) {
    asm volatile("cp.async.cg.shared.global [%0], [%1], 16;"
        :: "r"(dst), "l"(src));
}
#define CP_COMMIT() asm volatile("cp.async.commit_group;")
#define CP_WAIT0()  asm volatile("cp.async.wait_group 0;")

// ============================================================================
// Convert: x and 4 weight matrices -> fp16 (float4-vectorized)
// ============================================================================
__global__ __launch_bounds__(256) void split_kernel(
    const float* __restrict__ x,
    const float* __restrict__ Wq, const float* __restrict__ Wk,
    const float* __restrict__ Wv, const float* __restrict__ Wo)
{
    const int i4 = (blockIdx.x * 256 + threadIdx.x) * 4;
    const float* src;
    __half* dst;
    if (i4 < NELEM) {
        src = x + i4;
        dst = g_xh + i4;
    } else {
        const int j4 = i4 - NELEM;
        const int w  = j4 >> 20;
        const int off = j4 & (WELEM - 1);
        const float* W = (w == 0) ? Wq : (w == 1) ? Wk : (w == 2) ? Wv : Wo;
        src = W + off;
        dst = g_wh + j4;
    }
    const float4 v = *reinterpret_cast<const float4*>(src);
    uint2 p;
    p.x = pack2h(v.x, v.y);
    p.y = pack2h(v.z, v.w);
    *reinterpret_cast<uint2*>(dst) = p;
}

// ============================================================================
// fp16 GEMM:  C[m,n] = sum_k A[m,k]*W[n,k] + bias[n]
// BM=128, BN=128, BK=64, 256 thr (4m x 2n warps, warp tile 32x64).
// Single-sync pipeline: wait -> sync -> issue next stage -> compute.
// OutMode: 0 = fp32 out, 1 = fp16 out.
// ============================================================================
#define GROW 72
#define GT   (128 * GROW)      // halves per array per stage

template<int OutMode>
__device__ __forceinline__ void gemm_core(
    const __half* __restrict__ Ah, const __half* __restrict__ Wh,
    const float* __restrict__ bias,
    float* __restrict__ outF, __half* __restrict__ Oh)
{
    extern __shared__ __half sm[];
    const int tid  = threadIdx.x;
    const int lane = tid & 31;
    const int wid  = tid >> 5;
    const int wm   = wid & 3;
    const int wn   = wid >> 2;
    const int g    = lane >> 2;
    const int t4   = lane & 3;
    const int bm   = blockIdx.y * 128;
    const int bn   = blockIdx.x * 128;

    float acc[2][8][4];
#pragma unroll
    for (int s = 0; s < 2; ++s)
#pragma unroll
        for (int j = 0; j < 8; ++j)
#pragma unroll
            for (int e = 0; e < 4; ++e) acc[s][j][e] = 0.0f;

    // stage: 2 arrays x 128 rows x 64 halves; 2048 cp16; 8 per thread
    auto load_stage = [&](int s, int kt) {
#pragma unroll
        for (int i = 0; i < 8; ++i) {
            const int idx = i * 256 + tid;        // [0, 2048)
            const int a   = idx >> 10;            // 0:A 1:W
            const int rem = idx & 1023;
            const int row = rem >> 3;             // 0..127
            const int col = (rem & 7) * 8;        // 0..56
            const __half* base = (a == 0) ? Ah : Wh;
            const int rb = (a == 0) ? bm : bn;
            cp16(smem_u32(sm + (s * 2 + a) * GT + row * GROW + col),
                 base + (size_t)(rb + row) * E_DIM + kt + col);
        }
    };

    load_stage(0, 0);
    CP_COMMIT();

    const int NT = E_DIM / 64;   // 16
    for (int t = 0; t < NT; ++t) {
        const int s = t & 1;
        CP_WAIT0();              // my stage-s portions arrived
        __syncthreads();         // everyone's stage-s data published;
                                 // all warps done reading stage s^1
        if (t + 1 < NT) {
            load_stage(s ^ 1, (t + 1) * 64);   // overwrites stage read at t-1
            CP_COMMIT();
        }

        const uint32_t bAh = smem_u32(sm + (s * 2 + 0) * GT);
        const uint32_t bWh = smem_u32(sm + (s * 2 + 1) * GT);

#pragma unroll
        for (int kk = 0; kk < 4; ++kk) {
            uint32_t ah[2][4];
            const int ka = kk * 16 + (lane >> 4) * 8;
#pragma unroll
            for (int ss = 0; ss < 2; ++ss) {
                const int m = wm * 32 + ss * 16 + (lane & 15);
                const uint32_t off = (uint32_t)(m * GROW + ka) * 2;
                ldsm4(ah[ss][0], ah[ss][1], ah[ss][2], ah[ss][3], bAh + off);
            }
            const int kb  = kk * 16 + ((lane >> 3) & 1) * 8;
            const int nb0 = (lane & 7) + ((lane >> 4) << 3);
#pragma unroll
            for (int jp = 0; jp < 4; ++jp) {
                const int n = wn * 64 + jp * 16 + nb0;
                const uint32_t off = (uint32_t)(n * GROW + kb) * 2;
                uint32_t bh[4];
                ldsm4(bh[0], bh[1], bh[2], bh[3], bWh + off);
#pragma unroll
                for (int ss = 0; ss < 2; ++ss) {
                    mma_f16(acc[ss][2*jp],   ah[ss][0],ah[ss][1],ah[ss][2],ah[ss][3], bh[0],bh[1]);
                    mma_f16(acc[ss][2*jp+1], ah[ss][0],ah[ss][1],ah[ss][2],ah[ss][3], bh[2],bh[3]);
                }
            }
        }
    }

    // epilogue
#pragma unroll
    for (int j = 0; j < 8; ++j) {
        const int col = bn + wn * 64 + j * 8 + 2 * t4;
        const float b0 = bias[col], b1 = bias[col + 1];
#pragma unroll
        for (int ss = 0; ss < 2; ++ss) {
            const int r0 = bm + wm * 32 + ss * 16 + g;
            const float v0 = acc[ss][j][0] + b0, v1 = acc[ss][j][1] + b1;
            const float v2 = acc[ss][j][2] + b0, v3 = acc[ss][j][3] + b1;
            const size_t w0 = ((size_t)r0 * E_DIM + col) >> 1;
            const size_t w1 = ((size_t)(r0 + 8) * E_DIM + col) >> 1;
            if (OutMode == 1) {
                reinterpret_cast<uint32_t*>(Oh)[w0] = pack2h(v0, v1);
                reinterpret_cast<uint32_t*>(Oh)[w1] = pack2h(v2, v3);
            } else {
                float2 p0; p0.x = v0; p0.y = v1;
                float2 p1; p1.x = v2; p1.y = v3;
                *reinterpret_cast<float2*>(outF + (size_t)r0 * E_DIM + col) = p0;
                *reinterpret_cast<float2*>(outF + (size_t)(r0 + 8) * E_DIM + col) = p1;
            }
        }
    }
}

__global__ __launch_bounds__(256, 2) void qkv_kernel(
    const float* __restrict__ bq, const float* __restrict__ bk,
    const float* __restrict__ bv)
{
    const int z = blockIdx.z;
    const __half* Wh = g_wh + (size_t)z * WELEM;
    const float* bias = (z == 0) ? bq : (z == 1) ? bk : bv;
    __half* Oh = (z == 0) ? g_qh : (z == 1) ? g_kh : g_vh;
    gemm_core<1>(g_xh, Wh, bias, nullptr, Oh);
}

__global__ __launch_bounds__(256, 2) void outproj_kernel(
    const float* __restrict__ bo, float* __restrict__ out)
{
    gemm_core<0>(g_ah, g_wh + (size_t)3 * WELEM, bo, out, nullptr);
}

// ============================================================================
// Flash attention: 256 thr (8 warps), Q tile 128, K tiles of 64.
// Single-sync pipeline (same ordering as GEMM).
// QK^T: 1 MMA.  PV: 1 MMA.  Output fp16.
// ============================================================================
#define APAD 72
#define AT   (64 * APAD)
#define ATTN_SMEM (2 * 2 * AT * 2)   // 36864 B

__global__ __launch_bounds__(256) void attn_kernel()
{
    extern __shared__ __half sm[];
    const int tid  = threadIdx.x;
    const int lane = tid & 31;
    const int wid  = tid >> 5;          // 0..7
    const int g    = lane >> 2;
    const int t4   = lane & 3;

    const int bh = blockIdx.y;
    const int b  = bh >> 4;
    const int h  = bh & 15;
    const int q0 = blockIdx.x * 128 + wid * 16;
    const size_t qrow0 = (size_t)(b * S_LEN + q0);

    const float cs = 0.18033688011112042f;   // (1/8) * log2(e)

    uint32_t qfh[4][4];
#pragma unroll
    for (int kk = 0; kk < 4; ++kk) {
        const size_t i0 = (qrow0 + g) * E_DIM + h * HD + kk * 16 + 2 * t4;
        const size_t i1 = (qrow0 + g + 8) * E_DIM + h * HD + kk * 16 + 2 * t4;
        qfh[kk][0] = *reinterpret_cast<const uint32_t*>(g_qh + i0);
        qfh[kk][1] = *reinterpret_cast<const uint32_t*>(g_qh + i1);
        qfh[kk][2] = *reinterpret_cast<const uint32_t*>(g_qh + i0 + 8);
        qfh[kk][3] = *reinterpret_cast<const uint32_t*>(g_qh + i1 + 8);
    }

    float oacc[8][4];
#pragma unroll
    for (int jd = 0; jd < 8; ++jd)
#pragma unroll
        for (int e = 0; e < 4; ++e) oacc[jd][e] = 0.0f;
    float m0 = -INFINITY, m1 = -INFINITY, l0 = 0.0f, l1 = 0.0f;

    auto load_stage = [&](int s, int kt) {
#pragma unroll
        for (int i = 0; i < 4; ++i) {
            const int idx = i * 256 + tid;       // [0, 1024)
            const int a   = idx >> 9;            // 0:Kh 1:Vh
            const int rem = idx & 511;
            const int row = rem >> 3;            // 0..63
            const int col = (rem & 7) * 8;
            const __half* base = (a == 0) ? g_kh : g_vh;
            cp16(smem_u32(sm + (s * 2 + a) * AT + row * APAD + col),
                 base + (size_t)(b * S_LEN + kt * 64 + row) * E_DIM + h * HD + col);
        }
    };

    load_stage(0, 0);
    CP_COMMIT();

    const int NT = S_LEN / 64;
    for (int t = 0; t < NT; ++t) {
        const int s = t & 1;
        CP_WAIT0();
        __syncthreads();
        if (t + 1 < NT) {
            load_stage(s ^ 1, t + 1);
            CP_COMMIT();
        }

        const uint32_t bKh = smem_u32(sm + (s * 2 + 0) * AT);
        const uint32_t bVh = smem_u32(sm + (s * 2 + 1) * AT);

        // ---- QK^T ----
        float sacc[8][4];
#pragma unroll
        for (int j = 0; j < 8; ++j)
#pragma unroll
            for (int e = 0; e < 4; ++e) sacc[j][e] = 0.0f;

        const int nb0 = (lane & 7) + ((lane >> 4) << 3);
        const int kb0 = ((lane >> 3) & 1) * 8;
#pragma unroll
        for (int jp = 0; jp < 4; ++jp) {
            const int n = jp * 16 + nb0;
#pragma unroll
            for (int kk = 0; kk < 4; ++kk) {
                const uint32_t off = (uint32_t)(n * APAD + kk * 16 + kb0) * 2;
                uint32_t kh[4];
                ldsm4(kh[0], kh[1], kh[2], kh[3], bKh + off);
                mma_f16(sacc[2*jp],   qfh[kk][0],qfh[kk][1],qfh[kk][2],qfh[kk][3], kh[0],kh[1]);
                mma_f16(sacc[2*jp+1], qfh[kk][0],qfh[kk][1],qfh[kk][2],qfh[kk][3], kh[2],kh[3]);
            }
        }

        // ---- online softmax ----
        float nm0 = m0, nm1 = m1;
#pragma unroll
        for (int j = 0; j < 8; ++j) {
            nm0 = fmaxf(nm0, fmaxf(sacc[j][0], sacc[j][1]));
            nm1 = fmaxf(nm1, fmaxf(sacc[j][2], sacc[j][3]));
        }
        nm0 = fmaxf(nm0, __shfl_xor_sync(0xffffffffu, nm0, 1));
        nm0 = fmaxf(nm0, __shfl_xor_sync(0xffffffffu, nm0, 2));
        nm1 = fmaxf(nm1, __shfl_xor_sync(0xffffffffu, nm1, 1));
        nm1 = fmaxf(nm1, __shfl_xor_sync(0xffffffffu, nm1, 2));

        const float c0 = ex2f((m0 - nm0) * cs);
        const float c1 = ex2f((m1 - nm1) * cs);
        m0 = nm0; m1 = nm1;
        l0 *= c0;  l1 *= c1;

#pragma unroll
        for (int j = 0; j < 8; ++j) {
            const float p0 = ex2f((sacc[j][0] - m0) * cs);
            const float p1 = ex2f((sacc[j][1] - m0) * cs);
            const float p2 = ex2f((sacc[j][2] - m1) * cs);
            const float p3 = ex2f((sacc[j][3] - m1) * cs);
            l0 += p0 + p1;
            l1 += p2 + p3;
            sacc[j][0] = p0; sacc[j][1] = p1; sacc[j][2] = p2; sacc[j][3] = p3;
        }
#pragma unroll
        for (int jd = 0; jd < 8; ++jd) {
            oacc[jd][0] *= c0; oacc[jd][1] *= c0;
            oacc[jd][2] *= c1; oacc[jd][3] *= c1;
        }

        // ---- PV ----
        const int krb = ((lane >> 3) & 1) * 8 + (lane & 7);
        const int dcb = (lane >> 4) * 8;
#pragma unroll
        for (int kk = 0; kk < 4; ++kk) {
            uint32_t pah[4];
            pah[0] = pack2h(sacc[2*kk][0],   sacc[2*kk][1]);
            pah[1] = pack2h(sacc[2*kk][2],   sacc[2*kk][3]);
            pah[2] = pack2h(sacc[2*kk+1][0], sacc[2*kk+1][1]);
            pah[3] = pack2h(sacc[2*kk+1][2], sacc[2*kk+1][3]);
            const int kr = kk * 16 + krb;
#pragma unroll
            for (int jdp = 0; jdp < 4; ++jdp) {
                const int dc = jdp * 16 + dcb;
                const uint32_t off = (uint32_t)(kr * APAD + dc) * 2;
                uint32_t vh[4];
                ldsm4t(vh[0], vh[1], vh[2], vh[3], bVh + off);
                mma_f16(oacc[2*jdp],   pah[0],pah[1],pah[2],pah[3], vh[0],vh[1]);
                mma_f16(oacc[2*jdp+1], pah[0],pah[1],pah[2],pah[3], vh[2],vh[3]);
            }
        }
    }

    // ---- finalize: fp16 output ----
    l0 += __shfl_xor_sync(0xffffffffu, l0, 1);
    l0 += __shfl_xor_sync(0xffffffffu, l0, 2);
    l1 += __shfl_xor_sync(0xffffffffu, l1, 1);
    l1 += __shfl_xor_sync(0xffffffffu, l1, 2);
    const float inv0 = 1.0f / l0;
    const float inv1 = 1.0f / l1;

#pragma unroll
    for (int jd = 0; jd < 8; ++jd) {
        const int col = h * HD + jd * 8 + 2 * t4;
        const size_t w0 = ((qrow0 + g) * E_DIM + col) >> 1;
        const size_t w1 = ((qrow0 + g + 8) * E_DIM + col) >> 1;
        reinterpret_cast<uint32_t*>(g_ah)[w0] =
            pack2h(oacc[jd][0] * inv0, oacc[jd][1] * inv0);
        reinterpret_cast<uint32_t*>(g_ah)[w1] =
            pack2h(oacc[jd][2] * inv1, oacc[jd][3] * inv1);
    }
}

// ============================================================================
// Launch
// ============================================================================
#define GEMM_SMEM (2 * 2 * GT * 2)   // 73728 bytes

extern "C" void kernel_launch(void* const* d_in, const int* in_sizes, int n_in,
                              void* d_out, int out_size)
{
    const float* x  = (const float*)d_in[0];
    const float* bq = (const float*)d_in[2];
    const float* bk = (const float*)d_in[4];
    const float* bv = (const float*)d_in[6];
    const float* bo = (const float*)d_in[8];
    float* out = (float*)d_out;

    cudaFuncSetAttribute(qkv_kernel,
        cudaFuncAttributeMaxDynamicSharedMemorySize, GEMM_SMEM);
    cudaFuncSetAttribute(outproj_kernel,
        cudaFuncAttributeMaxDynamicSharedMemorySize, GEMM_SMEM);
    cudaFuncSetAttribute(attn_kernel,
        cudaFuncAttributeMaxDynamicSharedMemorySize, ATTN_SMEM);

    // 0) convert x and weights to fp16
    {
        const int total = (NELEM + 4 * WELEM) / 4;
        split_kernel<<<total / 256, 256>>>(x,
            (const float*)d_in[1], (const float*)d_in[3],
            (const float*)d_in[5], (const float*)d_in[7]);
    }
    // 1) fused QKV projections
    {
        dim3 grid(E_DIM / 128, MAX_M / 128, 3);
        qkv_kernel<<<grid, 256, GEMM_SMEM>>>(bq, bk, bv);
    }
    // 2) flash attention
    {
        dim3 grid(S_LEN / 128, 2 * NH);
        attn_kernel<<<grid, 256, ATTN_SMEM>>>();
    }
    // 3) output projection
    {
        dim3 grid(E_DIM / 128, MAX_M / 128);
        outproj_kernel<<<grid, 256, GEMM_SMEM>>>(bo, out);
    }
}